// round 5
// baseline (speedup 1.0000x reference)
#include <cuda_runtime.h>
#include <cuda_fp16.h>
#include <cstdint>

#define H_HEADS   32
#define KV_HEADS  8
#define HEAD_DIM  128
#define HIDDEN    2048
#define QLEN      1024
#define CTXLEN    2048
#define TLEN      3072
#define QKDIM     (H_HEADS * HEAD_DIM)    // 4096
#define KVDIM     (KV_HEADS * HEAD_DIM)   // 1024

// ---------------- scratch ----------------
__device__ __half g_Xh  [TLEN * HIDDEN];
__device__ __half g_Wqh [QKDIM * HIDDEN];
__device__ __half g_Wkh [KVDIM * HIDDEN];
__device__ __half g_Wvh [KVDIM * HIDDEN];
__device__ __half g_Woh [HIDDEN * QKDIM];
__device__ float  g_Qraw[QLEN * QKDIM];
__device__ float  g_Kraw[TLEN * KVDIM];
__device__ __half g_Qh  [QLEN * QKDIM];
__device__ __half g_Kh  [TLEN * KVDIM];
__device__ __half g_Vh  [TLEN * KVDIM];
__device__ __half g_Oh  [QLEN * QKDIM];

// ---------------- helpers ----------------
__device__ __forceinline__ uint32_t smem_u32(const void* p) {
    return (uint32_t)__cvta_generic_to_shared(p);
}
__device__ __forceinline__ void ldsm4(uint32_t& r0, uint32_t& r1, uint32_t& r2, uint32_t& r3, uint32_t a) {
    asm volatile("ldmatrix.sync.aligned.m8n8.x4.shared.b16 {%0,%1,%2,%3},[%4];\n"
                 : "=r"(r0), "=r"(r1), "=r"(r2), "=r"(r3) : "r"(a));
}
__device__ __forceinline__ void ldsm4t(uint32_t& r0, uint32_t& r1, uint32_t& r2, uint32_t& r3, uint32_t a) {
    asm volatile("ldmatrix.sync.aligned.m8n8.x4.trans.shared.b16 {%0,%1,%2,%3},[%4];\n"
                 : "=r"(r0), "=r"(r1), "=r"(r2), "=r"(r3) : "r"(a));
}
__device__ __forceinline__ void mma16816(float* c, uint32_t a0, uint32_t a1, uint32_t a2, uint32_t a3,
                                         uint32_t b0, uint32_t b1) {
    asm volatile("mma.sync.aligned.m16n8k16.row.col.f32.f16.f16.f32 "
                 "{%0,%1,%2,%3},{%4,%5,%6,%7},{%8,%9},{%0,%1,%2,%3};\n"
                 : "+f"(c[0]), "+f"(c[1]), "+f"(c[2]), "+f"(c[3])
                 : "r"(a0), "r"(a1), "r"(a2), "r"(a3), "r"(b0), "r"(b1));
}
__device__ __forceinline__ uint32_t packh2(float a, float b) {
    __half2 h = __floats2half2_rn(a, b);
    return *reinterpret_cast<uint32_t*>(&h);
}
__device__ __forceinline__ void cpa16(uint32_t dst, const void* src) {
    asm volatile("cp.async.cg.shared.global [%0],[%1],16;\n" :: "r"(dst), "l"(src));
}
__device__ __forceinline__ void cpa_commit() { asm volatile("cp.async.commit_group;\n"); }
template <int N> __device__ __forceinline__ void cpa_wait() {
    asm volatile("cp.async.wait_group %0;\n" :: "n"(N));
}
__device__ __forceinline__ void st2(float* p, float a, float b) { *(float2*)p = make_float2(a, b); }
__device__ __forceinline__ void st2(__half* p, float a, float b) { *(__half2*)p = __floats2half2_rn(a, b); }

// ---------------- fp32 -> fp16 conversion ----------------
__global__ void cvt_f2h(const float* __restrict__ src, __half* __restrict__ dst, int n4) {
    int i = blockIdx.x * blockDim.x + threadIdx.x;
    int stride = gridDim.x * blockDim.x;
    for (; i < n4; i += stride) {
        float4 v = reinterpret_cast<const float4*>(src)[i];
        reinterpret_cast<__half2*>(dst)[2 * i]     = __floats2half2_rn(v.x, v.y);
        reinterpret_cast<__half2*>(dst)[2 * i + 1] = __floats2half2_rn(v.z, v.w);
    }
}

// =========================================================================
// GEMM: C[M,N] = A[M,K] * B[N,K]^T, fp16 in, fp32 acc, OutT out.
// BM=256 BN=128 BK=32, 512 threads (16 warps, 8x2), 3-stage cp.async,
// one __syncthreads per k-iteration.
// =========================================================================
#define GSA 40
#define G_STAGES 3
#define G_ASTRIDE (256 * GSA)
#define G_BSTRIDE (128 * GSA)
#define G_SMEM (G_STAGES * (G_ASTRIDE + G_BSTRIDE) * 2)

template <typename OutT>
__global__ __launch_bounds__(512) void gemm_f16(const __half* __restrict__ A,
                                                const __half* __restrict__ B,
                                                OutT* __restrict__ C,
                                                int M, int N, int K) {
    extern __shared__ __align__(16) __half gsm[];
    __half* As = gsm;                       // [3][256*GSA]
    __half* Bs = gsm + G_STAGES * G_ASTRIDE; // [3][128*GSA]
    const int tid = threadIdx.x, lane = tid & 31, w = tid >> 5;
    const int bm = blockIdx.y << 8, bn = blockIdx.x << 7;
    const int wm = (w >> 1) << 5, wn = (w & 1) << 6;

    float acc[2][8][4];
#pragma unroll
    for (int i = 0; i < 2; i++)
#pragma unroll
        for (int j = 0; j < 8; j++)
#pragma unroll
            for (int k = 0; k < 4; k++) acc[i][j][k] = 0.f;

    const int r = tid >> 2, cch = (tid & 3) << 3;
    const int nt = K >> 5;

    auto load_stage = [&](int t, int s) {
        int k0 = t << 5;
        cpa16(smem_u32(&As[s * G_ASTRIDE + r * GSA + cch]),
              &A[(size_t)(bm + r) * K + k0 + cch]);
        cpa16(smem_u32(&As[s * G_ASTRIDE + (r + 128) * GSA + cch]),
              &A[(size_t)(bm + r + 128) * K + k0 + cch]);
        cpa16(smem_u32(&Bs[s * G_BSTRIDE + r * GSA + cch]),
              &B[(size_t)(bn + r) * K + k0 + cch]);
    };

    load_stage(0, 0); cpa_commit();
    if (nt > 1) { load_stage(1, 1); cpa_commit(); }

    int s_cur = 0, s_pre = 2;          // stage being computed / stage to prefetch into
    for (int t = 0; t < nt; t++) {
        cpa_wait<1>();
        __syncthreads();
        if (t + 2 < nt) load_stage(t + 2, s_pre);
        cpa_commit();

        const __half* as = As + s_cur * G_ASTRIDE;
        const __half* bs = Bs + s_cur * G_BSTRIDE;
#pragma unroll
        for (int kk = 0; kk < 2; kk++) {
            uint32_t a[2][4];
#pragma unroll
            for (int mt = 0; mt < 2; mt++) {
                uint32_t ad = smem_u32(&as[(wm + mt * 16 + (lane & 15)) * GSA + kk * 16 + ((lane >> 4) << 3)]);
                ldsm4(a[mt][0], a[mt][1], a[mt][2], a[mt][3], ad);
            }
#pragma unroll
            for (int n2 = 0; n2 < 4; n2++) {
                uint32_t b0, b1, b2, b3;
                uint32_t ad = smem_u32(&bs[(wn + n2 * 16 + ((lane >> 4) << 3) + (lane & 7)) * GSA +
                                           kk * 16 + (((lane >> 3) & 1) << 3)]);
                ldsm4(b0, b1, b2, b3, ad);
#pragma unroll
                for (int mt = 0; mt < 2; mt++) {
                    mma16816(acc[mt][2 * n2],     a[mt][0], a[mt][1], a[mt][2], a[mt][3], b0, b1);
                    mma16816(acc[mt][2 * n2 + 1], a[mt][0], a[mt][1], a[mt][2], a[mt][3], b2, b3);
                }
            }
        }
        s_pre = s_cur;
        s_cur = (s_cur == G_STAGES - 1) ? 0 : s_cur + 1;
    }

    const int g = lane >> 2, c = (lane & 3) << 1;
#pragma unroll
    for (int mt = 0; mt < 2; mt++)
#pragma unroll
        for (int ntl = 0; ntl < 8; ntl++) {
            int row = bm + wm + mt * 16 + g;
            int col = bn + wn + ntl * 8 + c;
            st2(&C[(size_t)row * N + col],       acc[mt][ntl][0], acc[mt][ntl][1]);
            st2(&C[(size_t)(row + 8) * N + col], acc[mt][ntl][2], acc[mt][ntl][3]);
        }
}

// ---------------- RMSNorm + RoPE ----------------
__global__ void norm_rope(const float* __restrict__ src, const float* __restrict__ cosp,
                          const float* __restrict__ sinp, const float* __restrict__ wnorm,
                          __half* __restrict__ dst, int nheads, int pos_off, float outscale) {
    const int row = blockIdx.x, h = blockIdx.y, d = threadIdx.x;
    const int stride = nheads * HEAD_DIM;
    const size_t base = (size_t)row * stride + h * HEAD_DIM;
    float x = src[base + d];
    float ss = x * x;
#pragma unroll
    for (int o = 16; o; o >>= 1) ss += __shfl_xor_sync(0xffffffffu, ss, o);
    __shared__ float ws[4];
    const int lane = d & 31, warp = d >> 5;
    if (lane == 0) ws[warp] = ss;
    __syncthreads();
    float sum = ws[0] + ws[1] + ws[2] + ws[3];
    float y = x * rsqrtf(sum * (1.0f / HEAD_DIM) + 1e-6f) * wnorm[d];
    __shared__ float ys[HEAD_DIM];
    ys[d] = y;
    __syncthreads();
    float partner = (d < 64) ? -ys[d + 64] : ys[d - 64];
    int pos = pos_off + row;
    float o = y * cosp[pos * HEAD_DIM + d] + partner * sinp[pos * HEAD_DIM + d];
    dst[base + d] = __float2half(o * outscale);
}

// ---------------- flash attention: 128 q/CTA, 8 warps, cp.async 2-stage, exp2 ------
#define FPAD 136
__global__ __launch_bounds__(256) void flash(const __half* __restrict__ Qh,
                                             const __half* __restrict__ Kh,
                                             const __half* __restrict__ Vh,
                                             __half* __restrict__ Oh) {
    extern __shared__ __align__(16) __half fsm[];
    __half* sK = fsm;
    __half* sV = fsm + 2 * 64 * FPAD;
    const int tid = threadIdx.x, lane = tid & 31, w = tid >> 5;
    const int bx = gridDim.x - 1 - blockIdx.x;
    const int qb = bx << 7;
    const int h = blockIdx.y;
    const int kv = h >> 2;

    {
        const __half* Qp = Qh + (size_t)qb * QKDIM + h * HEAD_DIM;
        for (int i = tid; i < 128 * 16; i += 256) {
            int r = i >> 4, c = (i & 15) << 3;
            *(uint4*)&sK[r * FPAD + c] = *(const uint4*)&Qp[(size_t)r * QKDIM + c];
        }
    }
    __syncthreads();
    uint32_t qa[8][4];
#pragma unroll
    for (int kt = 0; kt < 8; kt++) {
        uint32_t ad = smem_u32(&sK[(w * 16 + (lane & 15)) * FPAD + kt * 16 + ((lane >> 4) << 3)]);
        ldsm4(qa[kt][0], qa[kt][1], qa[kt][2], qa[kt][3], ad);
    }
    __syncthreads();

    float O[16][4];
#pragma unroll
    for (int i = 0; i < 16; i++)
#pragma unroll
        for (int j = 0; j < 4; j++) O[i][j] = 0.f;
    float m0 = -1e30f, m1 = -1e30f, l0 = 0.f, l1 = 0.f;

    const int ntiles = 34 + (bx << 1);
    const __half* Kp = Kh + kv * HEAD_DIM;
    const __half* Vp = Vh + kv * HEAD_DIM;
    const int g = lane >> 2, c2 = (lane & 3) << 1;

    auto loadKV = [&](int t, int buf) {
        for (int i = tid; i < 64 * 16; i += 256) {
            int r = i >> 4, c = (i & 15) << 3;
            size_t go = (size_t)(t * 64 + r) * KVDIM + c;
            cpa16(smem_u32(&sK[(buf * 64 + r) * FPAD + c]), &Kp[go]);
            cpa16(smem_u32(&sV[(buf * 64 + r) * FPAD + c]), &Vp[go]);
        }
    };

    loadKV(0, 0);
    cpa_commit();

    for (int t = 0; t < ntiles; t++) {
        if (t + 1 < ntiles) loadKV(t + 1, (t + 1) & 1);
        cpa_commit();
        cpa_wait<1>();
        __syncthreads();
        const int buf = t & 1;
        const int krel0 = t * 64 - (CTXLEN + qb);

        if (krel0 <= w * 16 + 15) {
            float S[8][4];
#pragma unroll
            for (int i = 0; i < 8; i++)
#pragma unroll
                for (int j = 0; j < 4; j++) S[i][j] = 0.f;

#pragma unroll
            for (int kt = 0; kt < 8; kt++) {
#pragma unroll
                for (int n2 = 0; n2 < 4; n2++) {
                    uint32_t b0, b1, b2, b3;
                    uint32_t ad = smem_u32(&sK[(buf * 64 + n2 * 16 + ((lane >> 4) << 3) + (lane & 7)) * FPAD +
                                               kt * 16 + (((lane >> 3) & 1) << 3)]);
                    ldsm4(b0, b1, b2, b3, ad);
                    mma16816(S[2 * n2],     qa[kt][0], qa[kt][1], qa[kt][2], qa[kt][3], b0, b1);
                    mma16816(S[2 * n2 + 1], qa[kt][0], qa[kt][1], qa[kt][2], qa[kt][3], b2, b3);
                }
            }

            if (krel0 + 63 > w * 16) {
                int r0 = w * 16 + g - krel0, r1 = r0 + 8;
#pragma unroll
                for (int ntl = 0; ntl < 8; ntl++) {
                    int col = ntl * 8 + c2;
                    if (col     > r0) S[ntl][0] = -1e30f;
                    if (col + 1 > r0) S[ntl][1] = -1e30f;
                    if (col     > r1) S[ntl][2] = -1e30f;
                    if (col + 1 > r1) S[ntl][3] = -1e30f;
                }
            }

            float mt0 = -1e30f, mt1 = -1e30f;
#pragma unroll
            for (int ntl = 0; ntl < 8; ntl++) {
                mt0 = fmaxf(mt0, fmaxf(S[ntl][0], S[ntl][1]));
                mt1 = fmaxf(mt1, fmaxf(S[ntl][2], S[ntl][3]));
            }
            mt0 = fmaxf(mt0, __shfl_xor_sync(0xffffffffu, mt0, 1));
            mt0 = fmaxf(mt0, __shfl_xor_sync(0xffffffffu, mt0, 2));
            mt1 = fmaxf(mt1, __shfl_xor_sync(0xffffffffu, mt1, 1));
            mt1 = fmaxf(mt1, __shfl_xor_sync(0xffffffffu, mt1, 2));
            float mn0 = fmaxf(m0, mt0), mn1 = fmaxf(m1, mt1);
            float s0 = 0.f, s1 = 0.f;
#pragma unroll
            for (int ntl = 0; ntl < 8; ntl++) {
                S[ntl][0] = exp2f(S[ntl][0] - mn0); s0 += S[ntl][0];
                S[ntl][1] = exp2f(S[ntl][1] - mn0); s0 += S[ntl][1];
                S[ntl][2] = exp2f(S[ntl][2] - mn1); s1 += S[ntl][2];
                S[ntl][3] = exp2f(S[ntl][3] - mn1); s1 += S[ntl][3];
            }
            s0 += __shfl_xor_sync(0xffffffffu, s0, 1);
            s0 += __shfl_xor_sync(0xffffffffu, s0, 2);
            s1 += __shfl_xor_sync(0xffffffffu, s1, 1);
            s1 += __shfl_xor_sync(0xffffffffu, s1, 2);

            if (mn0 > m0 || mn1 > m1) {
                float a0 = exp2f(m0 - mn0), a1 = exp2f(m1 - mn1);
                l0 *= a0; l1 *= a1;
#pragma unroll
                for (int ntl = 0; ntl < 16; ntl++) {
                    O[ntl][0] *= a0; O[ntl][1] *= a0; O[ntl][2] *= a1; O[ntl][3] *= a1;
                }
            }
            m0 = mn0; m1 = mn1;
            l0 += s0; l1 += s1;

#pragma unroll
            for (int kc = 0; kc < 4; kc++) {
                uint32_t A0 = packh2(S[2 * kc][0],     S[2 * kc][1]);
                uint32_t A1 = packh2(S[2 * kc][2],     S[2 * kc][3]);
                uint32_t A2 = packh2(S[2 * kc + 1][0], S[2 * kc + 1][1]);
                uint32_t A3 = packh2(S[2 * kc + 1][2], S[2 * kc + 1][3]);
#pragma unroll
                for (int d2 = 0; d2 < 8; d2++) {
                    uint32_t v0, v1, v2, v3;
                    uint32_t ad = smem_u32(&sV[(buf * 64 + kc * 16 + (lane & 15)) * FPAD +
                                               d2 * 16 + ((lane >> 4) << 3)]);
                    ldsm4t(v0, v1, v2, v3, ad);
                    mma16816(O[2 * d2],     A0, A1, A2, A3, v0, v1);
                    mma16816(O[2 * d2 + 1], A0, A1, A2, A3, v2, v3);
                }
            }
        }
        __syncthreads();
    }

    float i0 = 1.f / l0, i1 = 1.f / l1;
    __half* Op = Oh + (size_t)(qb + w * 16) * QKDIM + h * HEAD_DIM;
#pragma unroll
    for (int ntl = 0; ntl < 16; ntl++) {
        int col = ntl * 8 + c2;
        *(__half2*)&Op[(size_t)g * QKDIM + col]       = __floats2half2_rn(O[ntl][0] * i0, O[ntl][1] * i0);
        *(__half2*)&Op[(size_t)(g + 8) * QKDIM + col] = __floats2half2_rn(O[ntl][2] * i1, O[ntl][3] * i1);
    }
}

// ---------------- launcher ----------------
extern "C" void kernel_launch(void* const* d_in, const int* in_sizes, int n_in,
                              void* d_out, int out_size) {
    const float* hidden = (const float*)d_in[0];
    const float* target = (const float*)d_in[1];
    const float* cosp   = (const float*)d_in[2];
    const float* sinp   = (const float*)d_in[3];
    const float* wq = (const float*)d_in[5];
    const float* wk = (const float*)d_in[6];
    const float* wv = (const float*)d_in[7];
    const float* wo = (const float*)d_in[8];
    const float* qw = (const float*)d_in[9];
    const float* kw = (const float*)d_in[10];
    float* out = (float*)d_out;

    __half *Xh, *Wqh, *Wkh, *Wvh, *Woh, *Qh, *Kh, *Vh, *Oh;
    float *Qraw, *Kraw;
    cudaGetSymbolAddress((void**)&Xh, g_Xh);
    cudaGetSymbolAddress((void**)&Wqh, g_Wqh);
    cudaGetSymbolAddress((void**)&Wkh, g_Wkh);
    cudaGetSymbolAddress((void**)&Wvh, g_Wvh);
    cudaGetSymbolAddress((void**)&Woh, g_Woh);
    cudaGetSymbolAddress((void**)&Qraw, g_Qraw);
    cudaGetSymbolAddress((void**)&Kraw, g_Kraw);
    cudaGetSymbolAddress((void**)&Qh, g_Qh);
    cudaGetSymbolAddress((void**)&Kh, g_Kh);
    cudaGetSymbolAddress((void**)&Vh, g_Vh);
    cudaGetSymbolAddress((void**)&Oh, g_Oh);

    cudaFuncSetAttribute(gemm_f16<float>,  cudaFuncAttributeMaxDynamicSharedMemorySize, G_SMEM);
    cudaFuncSetAttribute(gemm_f16<__half>, cudaFuncAttributeMaxDynamicSharedMemorySize, G_SMEM);
    cudaFuncSetAttribute(flash, cudaFuncAttributeMaxDynamicSharedMemorySize, 4 * 64 * FPAD * 2);

    // launches 0-4: conversions needed before QKV projections
    cvt_f2h<<<512, 256>>>(target, Xh,                           CTXLEN * HIDDEN / 4);
    cvt_f2h<<<512, 256>>>(hidden, Xh + (size_t)CTXLEN * HIDDEN, QLEN * HIDDEN / 4);
    cvt_f2h<<<512, 256>>>(wq, Wqh, QKDIM * HIDDEN / 4);
    cvt_f2h<<<512, 256>>>(wk, Wkh, KVDIM * HIDDEN / 4);
    cvt_f2h<<<512, 256>>>(wv, Wvh, KVDIM * HIDDEN / 4);

    // launch 5: Q projection (ncu -s 5 profiles this)
    gemm_f16<float><<<dim3(QKDIM / 128, QLEN / 256), 512, G_SMEM>>>(
        Xh + (size_t)CTXLEN * HIDDEN, Wqh, Qraw, QLEN, QKDIM, HIDDEN);
    gemm_f16<float><<<dim3(KVDIM / 128, TLEN / 256), 512, G_SMEM>>>(
        Xh, Wkh, Kraw, TLEN, KVDIM, HIDDEN);
    gemm_f16<__half><<<dim3(KVDIM / 128, TLEN / 256), 512, G_SMEM>>>(
        Xh, Wvh, Vh, TLEN, KVDIM, HIDDEN);

    cvt_f2h<<<512, 256>>>(wo, Woh, HIDDEN * QKDIM / 4);

    // log2e folded into q scale so flash can use exp2
    norm_rope<<<dim3(QLEN, H_HEADS), 128>>>(Qraw, cosp, sinp, qw, Qh, H_HEADS, CTXLEN,
                                            0.08838834764831845f * 1.4426950408889634f);
    norm_rope<<<dim3(TLEN, KV_HEADS), 128>>>(Kraw, cosp, sinp, kw, Kh, KV_HEADS, 0, 1.0f);

    flash<<<dim3(QLEN / 128, H_HEADS), 256, 4 * 64 * FPAD * 2>>>(Qh, Kh, Vh, Oh);

    gemm_f16<float><<<dim3(HIDDEN / 128, QLEN / 256), 512, G_SMEM>>>(
        Oh, Woh, out, QLEN, HIDDEN, QKDIM);
}

// round 6
// speedup vs baseline: 1.2012x; 1.2012x over previous
#include <cuda_runtime.h>
#include <cuda_fp16.h>
#include <cstdint>

#define H_HEADS   32
#define KV_HEADS  8
#define HEAD_DIM  128
#define HIDDEN    2048
#define QLEN      1024
#define CTXLEN    2048
#define TLEN      3072
#define QKDIM     (H_HEADS * HEAD_DIM)    // 4096
#define KVDIM     (KV_HEADS * HEAD_DIM)   // 1024

// ---------------- scratch ----------------
__device__ __half g_Xh  [TLEN * HIDDEN];
__device__ __half g_Wqh [QKDIM * HIDDEN];
__device__ __half g_Wkvh[2 * KVDIM * HIDDEN];   // rows 0-1023: Wk, 1024-2047: Wv
__device__ __half g_Woh [HIDDEN * QKDIM];
__device__ float  g_Qraw[QLEN * QKDIM];
__device__ float  g_Kraw[TLEN * KVDIM];
__device__ __half g_Qh  [QLEN * QKDIM];
__device__ __half g_Kh  [TLEN * KVDIM];
__device__ __half g_Vh  [TLEN * KVDIM];
__device__ __half g_Oh  [QLEN * QKDIM];

// ---------------- helpers ----------------
__device__ __forceinline__ uint32_t smem_u32(const void* p) {
    return (uint32_t)__cvta_generic_to_shared(p);
}
__device__ __forceinline__ void ldsm4(uint32_t& r0, uint32_t& r1, uint32_t& r2, uint32_t& r3, uint32_t a) {
    asm volatile("ldmatrix.sync.aligned.m8n8.x4.shared.b16 {%0,%1,%2,%3},[%4];\n"
                 : "=r"(r0), "=r"(r1), "=r"(r2), "=r"(r3) : "r"(a));
}
__device__ __forceinline__ void ldsm4t(uint32_t& r0, uint32_t& r1, uint32_t& r2, uint32_t& r3, uint32_t a) {
    asm volatile("ldmatrix.sync.aligned.m8n8.x4.trans.shared.b16 {%0,%1,%2,%3},[%4];\n"
                 : "=r"(r0), "=r"(r1), "=r"(r2), "=r"(r3) : "r"(a));
}
__device__ __forceinline__ void mma16816(float* c, uint32_t a0, uint32_t a1, uint32_t a2, uint32_t a3,
                                         uint32_t b0, uint32_t b1) {
    asm volatile("mma.sync.aligned.m16n8k16.row.col.f32.f16.f16.f32 "
                 "{%0,%1,%2,%3},{%4,%5,%6,%7},{%8,%9},{%0,%1,%2,%3};\n"
                 : "+f"(c[0]), "+f"(c[1]), "+f"(c[2]), "+f"(c[3])
                 : "r"(a0), "r"(a1), "r"(a2), "r"(a3), "r"(b0), "r"(b1));
}
__device__ __forceinline__ uint32_t packh2(float a, float b) {
    __half2 h = __floats2half2_rn(a, b);
    return *reinterpret_cast<uint32_t*>(&h);
}
__device__ __forceinline__ void cpa16(uint32_t dst, const void* src) {
    asm volatile("cp.async.cg.shared.global [%0],[%1],16;\n" :: "r"(dst), "l"(src));
}
__device__ __forceinline__ void cpa_commit() { asm volatile("cp.async.commit_group;\n"); }
template <int N> __device__ __forceinline__ void cpa_wait() {
    asm volatile("cp.async.wait_group %0;\n" :: "n"(N));
}
__device__ __forceinline__ void st2(float* p, float a, float b) { *(float2*)p = make_float2(a, b); }
__device__ __forceinline__ void st2(__half* p, float a, float b) { *(__half2*)p = __floats2half2_rn(a, b); }

// ---------------- fused fp32 -> fp16 conversion (3 segments per launch) ----------------
__global__ void cvt3(const float* __restrict__ s0, __half* __restrict__ d0, int n0,
                     const float* __restrict__ s1, __half* __restrict__ d1, int n1,
                     const float* __restrict__ s2, __half* __restrict__ d2, int n2) {
    int total = n0 + n1 + n2;
    int stride = gridDim.x * blockDim.x;
    for (int i = blockIdx.x * blockDim.x + threadIdx.x; i < total; i += stride) {
        const float* s; __half* d; int j = i;
        if (j < n0)            { s = s0; d = d0; }
        else if (j < n0 + n1)  { s = s1; d = d1; j -= n0; }
        else                   { s = s2; d = d2; j -= n0 + n1; }
        float4 v = reinterpret_cast<const float4*>(s)[j];
        reinterpret_cast<__half2*>(d)[2 * j]     = __floats2half2_rn(v.x, v.y);
        reinterpret_cast<__half2*>(d)[2 * j + 1] = __floats2half2_rn(v.z, v.w);
    }
}

// =========================================================================
// GEMM core: C[M,N] = A[M,K] * B[N,K]^T, 128x128x32 tile, 256 thr, 3-stage
// cp.async, single __syncthreads per k-iter. KV variant splits the epilogue.
// =========================================================================
#define GSA 40
#define G_STAGES 3
#define G_TSTRIDE (128 * GSA)
#define G_SMEM (G_STAGES * G_TSTRIDE * 2 * 2)   // 61440 B

struct EpiPlain {};
struct EpiKV {};

template <typename OutT, typename Epi>
__global__ __launch_bounds__(256, 2) void gemm_f16(const __half* __restrict__ A,
                                                   const __half* __restrict__ B,
                                                   OutT* __restrict__ C,
                                                   void* __restrict__ C2,   // V half output (KV variant)
                                                   int M, int N, int K) {
    extern __shared__ __align__(16) __half gsm[];
    __half* As = gsm;                            // [3][128*GSA]
    __half* Bs = gsm + G_STAGES * G_TSTRIDE;
    const int tid = threadIdx.x, lane = tid & 31, w = tid >> 5;
    const int bm = blockIdx.y << 7, bn = blockIdx.x << 7;
    const int wm = (w >> 1) << 5, wn = (w & 1) << 6;

    float acc[2][8][4];
#pragma unroll
    for (int i = 0; i < 2; i++)
#pragma unroll
        for (int j = 0; j < 8; j++)
#pragma unroll
            for (int k = 0; k < 4; k++) acc[i][j][k] = 0.f;

    const int r = tid >> 2, cch = (tid & 3) << 3;
    const int nt = K >> 5;

    auto load_stage = [&](int t, int s) {
        int k0 = t << 5;
        cpa16(smem_u32(&As[s * G_TSTRIDE + r * GSA + cch]),
              &A[(size_t)(bm + r) * K + k0 + cch]);
        cpa16(smem_u32(&As[s * G_TSTRIDE + (r + 64) * GSA + cch]),
              &A[(size_t)(bm + r + 64) * K + k0 + cch]);
        cpa16(smem_u32(&Bs[s * G_TSTRIDE + r * GSA + cch]),
              &B[(size_t)(bn + r) * K + k0 + cch]);
        cpa16(smem_u32(&Bs[s * G_TSTRIDE + (r + 64) * GSA + cch]),
              &B[(size_t)(bn + r + 64) * K + k0 + cch]);
    };

    load_stage(0, 0); cpa_commit();
    load_stage(1, 1); cpa_commit();

    int s_cur = 0, s_pre = 2;
    for (int t = 0; t < nt; t++) {
        cpa_wait<1>();
        __syncthreads();
        if (t + 2 < nt) load_stage(t + 2, s_pre);
        cpa_commit();

        const __half* as = As + s_cur * G_TSTRIDE;
        const __half* bs = Bs + s_cur * G_TSTRIDE;
#pragma unroll
        for (int kk = 0; kk < 2; kk++) {
            uint32_t a[2][4];
#pragma unroll
            for (int mt = 0; mt < 2; mt++) {
                uint32_t ad = smem_u32(&as[(wm + mt * 16 + (lane & 15)) * GSA + kk * 16 + ((lane >> 4) << 3)]);
                ldsm4(a[mt][0], a[mt][1], a[mt][2], a[mt][3], ad);
            }
#pragma unroll
            for (int n2 = 0; n2 < 4; n2++) {
                uint32_t b0, b1, b2, b3;
                uint32_t ad = smem_u32(&bs[(wn + n2 * 16 + ((lane >> 4) << 3) + (lane & 7)) * GSA +
                                           kk * 16 + (((lane >> 3) & 1) << 3)]);
                ldsm4(b0, b1, b2, b3, ad);
#pragma unroll
                for (int mt = 0; mt < 2; mt++) {
                    mma16816(acc[mt][2 * n2],     a[mt][0], a[mt][1], a[mt][2], a[mt][3], b0, b1);
                    mma16816(acc[mt][2 * n2 + 1], a[mt][0], a[mt][1], a[mt][2], a[mt][3], b2, b3);
                }
            }
        }
        s_pre = s_cur;
        s_cur = (s_cur == G_STAGES - 1) ? 0 : s_cur + 1;
    }

    const int g = lane >> 2, c = (lane & 3) << 1;
    if constexpr (__is_same(Epi, EpiKV)) {
        // cols < KVDIM -> float K output; cols >= KVDIM -> half V output. bn is 128-aligned.
        const bool isK = bn < KVDIM;
        const int colbase = bn - (isK ? 0 : KVDIM) + wn;
#pragma unroll
        for (int mt = 0; mt < 2; mt++)
#pragma unroll
            for (int ntl = 0; ntl < 8; ntl++) {
                int row = bm + wm + mt * 16 + g;
                int col = colbase + ntl * 8 + c;
                if (isK) {
                    float* Cp = (float*)C;
                    st2(&Cp[(size_t)row * KVDIM + col],       acc[mt][ntl][0], acc[mt][ntl][1]);
                    st2(&Cp[(size_t)(row + 8) * KVDIM + col], acc[mt][ntl][2], acc[mt][ntl][3]);
                } else {
                    __half* Vp = (__half*)C2;
                    st2(&Vp[(size_t)row * KVDIM + col],       acc[mt][ntl][0], acc[mt][ntl][1]);
                    st2(&Vp[(size_t)(row + 8) * KVDIM + col], acc[mt][ntl][2], acc[mt][ntl][3]);
                }
            }
    } else {
#pragma unroll
        for (int mt = 0; mt < 2; mt++)
#pragma unroll
            for (int ntl = 0; ntl < 8; ntl++) {
                int row = bm + wm + mt * 16 + g;
                int col = bn + wn + ntl * 8 + c;
                st2(&C[(size_t)row * N + col],       acc[mt][ntl][0], acc[mt][ntl][1]);
                st2(&C[(size_t)(row + 8) * N + col], acc[mt][ntl][2], acc[mt][ntl][3]);
            }
    }
}

// ---------------- RMSNorm + RoPE ----------------
__global__ void norm_rope(const float* __restrict__ src, const float* __restrict__ cosp,
                          const float* __restrict__ sinp, const float* __restrict__ wnorm,
                          __half* __restrict__ dst, int nheads, int pos_off, float outscale) {
    const int row = blockIdx.x, h = blockIdx.y, d = threadIdx.x;
    const int stride = nheads * HEAD_DIM;
    const size_t base = (size_t)row * stride + h * HEAD_DIM;
    float x = src[base + d];
    float ss = x * x;
#pragma unroll
    for (int o = 16; o; o >>= 1) ss += __shfl_xor_sync(0xffffffffu, ss, o);
    __shared__ float ws[4];
    const int lane = d & 31, warp = d >> 5;
    if (lane == 0) ws[warp] = ss;
    __syncthreads();
    float sum = ws[0] + ws[1] + ws[2] + ws[3];
    float y = x * rsqrtf(sum * (1.0f / HEAD_DIM) + 1e-6f) * wnorm[d];
    __shared__ float ys[HEAD_DIM];
    ys[d] = y;
    __syncthreads();
    float partner = (d < 64) ? -ys[d + 64] : ys[d - 64];
    int pos = pos_off + row;
    float o = y * cosp[pos * HEAD_DIM + d] + partner * sinp[pos * HEAD_DIM + d];
    dst[base + d] = __float2half(o * outscale);
}

// ---------------- flash attention (round-2 proven version, exp2) ----------------
#define FPAD 136
__global__ __launch_bounds__(256) void flash(const __half* __restrict__ Qh,
                                             const __half* __restrict__ Kh,
                                             const __half* __restrict__ Vh,
                                             __half* __restrict__ Oh) {
    extern __shared__ __align__(16) __half fsm[];
    __half* sK = fsm;
    __half* sV = fsm + 2 * 64 * FPAD;
    const int tid = threadIdx.x, lane = tid & 31, w = tid >> 5;
    const int bx = gridDim.x - 1 - blockIdx.x;
    const int qb = bx << 7;
    const int h = blockIdx.y;
    const int kv = h >> 2;

    {
        const __half* Qp = Qh + (size_t)qb * QKDIM + h * HEAD_DIM;
        for (int i = tid; i < 128 * 16; i += 256) {
            int r = i >> 4, c = (i & 15) << 3;
            *(uint4*)&sK[r * FPAD + c] = *(const uint4*)&Qp[(size_t)r * QKDIM + c];
        }
    }
    __syncthreads();
    uint32_t qa[8][4];
#pragma unroll
    for (int kt = 0; kt < 8; kt++) {
        uint32_t ad = smem_u32(&sK[(w * 16 + (lane & 15)) * FPAD + kt * 16 + ((lane >> 4) << 3)]);
        ldsm4(qa[kt][0], qa[kt][1], qa[kt][2], qa[kt][3], ad);
    }
    __syncthreads();

    float O[16][4];
#pragma unroll
    for (int i = 0; i < 16; i++)
#pragma unroll
        for (int j = 0; j < 4; j++) O[i][j] = 0.f;
    float m0 = -1e30f, m1 = -1e30f, l0 = 0.f, l1 = 0.f;

    const int ntiles = 34 + (bx << 1);
    const __half* Kp = Kh + kv * HEAD_DIM;
    const __half* Vp = Vh + kv * HEAD_DIM;
    const int g = lane >> 2, c2 = (lane & 3) << 1;

    auto loadKV = [&](int t, int buf) {
        for (int i = tid; i < 64 * 16; i += 256) {
            int r = i >> 4, c = (i & 15) << 3;
            size_t go = (size_t)(t * 64 + r) * KVDIM + c;
            cpa16(smem_u32(&sK[(buf * 64 + r) * FPAD + c]), &Kp[go]);
            cpa16(smem_u32(&sV[(buf * 64 + r) * FPAD + c]), &Vp[go]);
        }
    };

    loadKV(0, 0);
    cpa_commit();

    for (int t = 0; t < ntiles; t++) {
        if (t + 1 < ntiles) loadKV(t + 1, (t + 1) & 1);
        cpa_commit();
        cpa_wait<1>();
        __syncthreads();
        const int buf = t & 1;
        const int krel0 = t * 64 - (CTXLEN + qb);

        if (krel0 <= w * 16 + 15) {
            float S[8][4];
#pragma unroll
            for (int i = 0; i < 8; i++)
#pragma unroll
                for (int j = 0; j < 4; j++) S[i][j] = 0.f;

#pragma unroll
            for (int kt = 0; kt < 8; kt++) {
#pragma unroll
                for (int n2 = 0; n2 < 4; n2++) {
                    uint32_t b0, b1, b2, b3;
                    uint32_t ad = smem_u32(&sK[(buf * 64 + n2 * 16 + ((lane >> 4) << 3) + (lane & 7)) * FPAD +
                                               kt * 16 + (((lane >> 3) & 1) << 3)]);
                    ldsm4(b0, b1, b2, b3, ad);
                    mma16816(S[2 * n2],     qa[kt][0], qa[kt][1], qa[kt][2], qa[kt][3], b0, b1);
                    mma16816(S[2 * n2 + 1], qa[kt][0], qa[kt][1], qa[kt][2], qa[kt][3], b2, b3);
                }
            }

            if (krel0 + 63 > w * 16) {
                int r0 = w * 16 + g - krel0, r1 = r0 + 8;
#pragma unroll
                for (int ntl = 0; ntl < 8; ntl++) {
                    int col = ntl * 8 + c2;
                    if (col     > r0) S[ntl][0] = -1e30f;
                    if (col + 1 > r0) S[ntl][1] = -1e30f;
                    if (col     > r1) S[ntl][2] = -1e30f;
                    if (col + 1 > r1) S[ntl][3] = -1e30f;
                }
            }

            float mt0 = -1e30f, mt1 = -1e30f;
#pragma unroll
            for (int ntl = 0; ntl < 8; ntl++) {
                mt0 = fmaxf(mt0, fmaxf(S[ntl][0], S[ntl][1]));
                mt1 = fmaxf(mt1, fmaxf(S[ntl][2], S[ntl][3]));
            }
            mt0 = fmaxf(mt0, __shfl_xor_sync(0xffffffffu, mt0, 1));
            mt0 = fmaxf(mt0, __shfl_xor_sync(0xffffffffu, mt0, 2));
            mt1 = fmaxf(mt1, __shfl_xor_sync(0xffffffffu, mt1, 1));
            mt1 = fmaxf(mt1, __shfl_xor_sync(0xffffffffu, mt1, 2));
            float mn0 = fmaxf(m0, mt0), mn1 = fmaxf(m1, mt1);
            float s0 = 0.f, s1 = 0.f;
#pragma unroll
            for (int ntl = 0; ntl < 8; ntl++) {
                S[ntl][0] = exp2f(S[ntl][0] - mn0); s0 += S[ntl][0];
                S[ntl][1] = exp2f(S[ntl][1] - mn0); s0 += S[ntl][1];
                S[ntl][2] = exp2f(S[ntl][2] - mn1); s1 += S[ntl][2];
                S[ntl][3] = exp2f(S[ntl][3] - mn1); s1 += S[ntl][3];
            }
            s0 += __shfl_xor_sync(0xffffffffu, s0, 1);
            s0 += __shfl_xor_sync(0xffffffffu, s0, 2);
            s1 += __shfl_xor_sync(0xffffffffu, s1, 1);
            s1 += __shfl_xor_sync(0xffffffffu, s1, 2);

            if (mn0 > m0 || mn1 > m1) {
                float a0 = exp2f(m0 - mn0), a1 = exp2f(m1 - mn1);
                l0 *= a0; l1 *= a1;
#pragma unroll
                for (int ntl = 0; ntl < 16; ntl++) {
                    O[ntl][0] *= a0; O[ntl][1] *= a0; O[ntl][2] *= a1; O[ntl][3] *= a1;
                }
            }
            m0 = mn0; m1 = mn1;
            l0 += s0; l1 += s1;

#pragma unroll
            for (int kc = 0; kc < 4; kc++) {
                uint32_t A0 = packh2(S[2 * kc][0],     S[2 * kc][1]);
                uint32_t A1 = packh2(S[2 * kc][2],     S[2 * kc][3]);
                uint32_t A2 = packh2(S[2 * kc + 1][0], S[2 * kc + 1][1]);
                uint32_t A3 = packh2(S[2 * kc + 1][2], S[2 * kc + 1][3]);
#pragma unroll
                for (int d2 = 0; d2 < 8; d2++) {
                    uint32_t v0, v1, v2, v3;
                    uint32_t ad = smem_u32(&sV[(buf * 64 + kc * 16 + (lane & 15)) * FPAD +
                                               d2 * 16 + ((lane >> 4) << 3)]);
                    ldsm4t(v0, v1, v2, v3, ad);
                    mma16816(O[2 * d2],     A0, A1, A2, A3, v0, v1);
                    mma16816(O[2 * d2 + 1], A0, A1, A2, A3, v2, v3);
                }
            }
        }
        __syncthreads();
    }

    float i0 = 1.f / l0, i1 = 1.f / l1;
    __half* Op = Oh + (size_t)(qb + w * 16) * QKDIM + h * HEAD_DIM;
#pragma unroll
    for (int ntl = 0; ntl < 16; ntl++) {
        int col = ntl * 8 + c2;
        *(__half2*)&Op[(size_t)g * QKDIM + col]       = __floats2half2_rn(O[ntl][0] * i0, O[ntl][1] * i0);
        *(__half2*)&Op[(size_t)(g + 8) * QKDIM + col] = __floats2half2_rn(O[ntl][2] * i1, O[ntl][3] * i1);
    }
}

// ---------------- launcher ----------------
extern "C" void kernel_launch(void* const* d_in, const int* in_sizes, int n_in,
                              void* d_out, int out_size) {
    const float* hidden = (const float*)d_in[0];
    const float* target = (const float*)d_in[1];
    const float* cosp   = (const float*)d_in[2];
    const float* sinp   = (const float*)d_in[3];
    const float* wq = (const float*)d_in[5];
    const float* wk = (const float*)d_in[6];
    const float* wv = (const float*)d_in[7];
    const float* wo = (const float*)d_in[8];
    const float* qw = (const float*)d_in[9];
    const float* kw = (const float*)d_in[10];
    float* out = (float*)d_out;

    __half *Xh, *Wqh, *Wkvh, *Woh, *Qh, *Kh, *Vh, *Oh;
    float *Qraw, *Kraw;
    cudaGetSymbolAddress((void**)&Xh, g_Xh);
    cudaGetSymbolAddress((void**)&Wqh, g_Wqh);
    cudaGetSymbolAddress((void**)&Wkvh, g_Wkvh);
    cudaGetSymbolAddress((void**)&Woh, g_Woh);
    cudaGetSymbolAddress((void**)&Qraw, g_Qraw);
    cudaGetSymbolAddress((void**)&Kraw, g_Kraw);
    cudaGetSymbolAddress((void**)&Qh, g_Qh);
    cudaGetSymbolAddress((void**)&Kh, g_Kh);
    cudaGetSymbolAddress((void**)&Vh, g_Vh);
    cudaGetSymbolAddress((void**)&Oh, g_Oh);

    cudaFuncSetAttribute((const void*)gemm_f16<float, EpiPlain>,
                         cudaFuncAttributeMaxDynamicSharedMemorySize, G_SMEM);
    cudaFuncSetAttribute((const void*)gemm_f16<float, EpiKV>,
                         cudaFuncAttributeMaxDynamicSharedMemorySize, G_SMEM);
    cudaFuncSetAttribute((const void*)flash,
                         cudaFuncAttributeMaxDynamicSharedMemorySize, 4 * 64 * FPAD * 2);

    // 2 fused conversion launches
    cvt3<<<1024, 256>>>(target, Xh, CTXLEN * HIDDEN / 4,
                        hidden, Xh + (size_t)CTXLEN * HIDDEN, QLEN * HIDDEN / 4,
                        wq, Wqh, QKDIM * HIDDEN / 4);
    cvt3<<<1024, 256>>>(wk, Wkvh, KVDIM * HIDDEN / 4,
                        wv, Wkvh + (size_t)KVDIM * HIDDEN, KVDIM * HIDDEN / 4,
                        wo, Woh, HIDDEN * QKDIM / 4);

    // Q projection
    gemm_f16<float, EpiPlain><<<dim3(QKDIM / 128, QLEN / 128), 256, G_SMEM>>>(
        Xh + (size_t)CTXLEN * HIDDEN, Wqh, Qraw, nullptr, QLEN, QKDIM, HIDDEN);
    // fused K+V projection: K -> Kraw (fp32), V -> Vh (fp16)
    gemm_f16<float, EpiKV><<<dim3(2 * KVDIM / 128, TLEN / 128), 256, G_SMEM>>>(
        Xh, Wkvh, Kraw, Vh, TLEN, 2 * KVDIM, HIDDEN);

    // rmsnorm + rope (attn scale * log2e folded into q for exp2 softmax)
    norm_rope<<<dim3(QLEN, H_HEADS), 128>>>(Qraw, cosp, sinp, qw, Qh, H_HEADS, CTXLEN,
                                            0.08838834764831845f * 1.4426950408889634f);
    norm_rope<<<dim3(TLEN, KV_HEADS), 128>>>(Kraw, cosp, sinp, kw, Kh, KV_HEADS, 0, 1.0f);

    flash<<<dim3(QLEN / 128, H_HEADS), 256, 4 * 64 * FPAD * 2>>>(Qh, Kh, Vh, Oh);

    gemm_f16<float, EpiPlain><<<dim3(HIDDEN / 128, QLEN / 128), 256, G_SMEM>>>(
        Oh, Woh, out, nullptr, QLEN, HIDDEN, QKDIM);
}

// round 7
// speedup vs baseline: 1.2315x; 1.0252x over previous
#include <cuda_runtime.h>
#include <cuda_fp16.h>
#include <cstdint>

#define H_HEADS   32
#define KV_HEADS  8
#define HEAD_DIM  128
#define HIDDEN    2048
#define QLEN      1024
#define CTXLEN    2048
#define TLEN      3072
#define QKDIM     (H_HEADS * HEAD_DIM)    // 4096
#define KVDIM     (KV_HEADS * HEAD_DIM)   // 1024

// ---------------- scratch ----------------
__device__ __half g_Xh  [TLEN * HIDDEN];
__device__ __half g_Wqh [QKDIM * HIDDEN];
__device__ __half g_Wkvh[2 * KVDIM * HIDDEN];   // rows 0-1023: Wk, 1024-2047: Wv
__device__ __half g_Woh [HIDDEN * QKDIM];
__device__ float  g_Qraw[QLEN * QKDIM];
__device__ float  g_Kraw[TLEN * KVDIM];
__device__ __half g_Qh  [QLEN * QKDIM];
__device__ __half g_Kh  [TLEN * KVDIM];
__device__ __half g_Vh  [TLEN * KVDIM];
__device__ __half g_Oh  [QLEN * QKDIM];

// ---------------- helpers ----------------
__device__ __forceinline__ uint32_t smem_u32(const void* p) {
    return (uint32_t)__cvta_generic_to_shared(p);
}
__device__ __forceinline__ void ldsm4(uint32_t& r0, uint32_t& r1, uint32_t& r2, uint32_t& r3, uint32_t a) {
    asm volatile("ldmatrix.sync.aligned.m8n8.x4.shared.b16 {%0,%1,%2,%3},[%4];\n"
                 : "=r"(r0), "=r"(r1), "=r"(r2), "=r"(r3) : "r"(a));
}
__device__ __forceinline__ void ldsm4t(uint32_t& r0, uint32_t& r1, uint32_t& r2, uint32_t& r3, uint32_t a) {
    asm volatile("ldmatrix.sync.aligned.m8n8.x4.trans.shared.b16 {%0,%1,%2,%3},[%4];\n"
                 : "=r"(r0), "=r"(r1), "=r"(r2), "=r"(r3) : "r"(a));
}
__device__ __forceinline__ void mma16816(float* c, uint32_t a0, uint32_t a1, uint32_t a2, uint32_t a3,
                                         uint32_t b0, uint32_t b1) {
    asm volatile("mma.sync.aligned.m16n8k16.row.col.f32.f16.f16.f32 "
                 "{%0,%1,%2,%3},{%4,%5,%6,%7},{%8,%9},{%0,%1,%2,%3};\n"
                 : "+f"(c[0]), "+f"(c[1]), "+f"(c[2]), "+f"(c[3])
                 : "r"(a0), "r"(a1), "r"(a2), "r"(a3), "r"(b0), "r"(b1));
}
__device__ __forceinline__ uint32_t packh2(float a, float b) {
    __half2 h = __floats2half2_rn(a, b);
    return *reinterpret_cast<uint32_t*>(&h);
}
__device__ __forceinline__ uint32_t h2exp2(uint32_t x) {
    uint32_t r;
    asm("ex2.approx.f16x2 %0, %1;" : "=r"(r) : "r"(x));
    return r;
}
__device__ __forceinline__ void cpa16(uint32_t dst, const void* src) {
    asm volatile("cp.async.cg.shared.global [%0],[%1],16;\n" :: "r"(dst), "l"(src));
}
__device__ __forceinline__ void cpa_commit() { asm volatile("cp.async.commit_group;\n"); }
template <int N> __device__ __forceinline__ void cpa_wait() {
    asm volatile("cp.async.wait_group %0;\n" :: "n"(N));
}
__device__ __forceinline__ void st2(float* p, float a, float b) { *(float2*)p = make_float2(a, b); }
__device__ __forceinline__ void st2(__half* p, float a, float b) { *(__half2*)p = __floats2half2_rn(a, b); }

// ---------------- fused fp32 -> fp16 conversion (3 segments per launch) ----------------
__global__ void cvt3(const float* __restrict__ s0, __half* __restrict__ d0, int n0,
                     const float* __restrict__ s1, __half* __restrict__ d1, int n1,
                     const float* __restrict__ s2, __half* __restrict__ d2, int n2) {
    int total = n0 + n1 + n2;
    int stride = gridDim.x * blockDim.x;
    for (int i = blockIdx.x * blockDim.x + threadIdx.x; i < total; i += stride) {
        const float* s; __half* d; int j = i;
        if (j < n0)            { s = s0; d = d0; }
        else if (j < n0 + n1)  { s = s1; d = d1; j -= n0; }
        else                   { s = s2; d = d2; j -= n0 + n1; }
        float4 v = reinterpret_cast<const float4*>(s)[j];
        reinterpret_cast<__half2*>(d)[2 * j]     = __floats2half2_rn(v.x, v.y);
        reinterpret_cast<__half2*>(d)[2 * j + 1] = __floats2half2_rn(v.z, v.w);
    }
}

// =========================================================================
// GEMM: C[M,N] = A[M,K] * B[N,K]^T, 128xNBx32 tile, 256 thr, 3-stage cp.async,
// single __syncthreads per k-iter. NB in {128, 64}. KV epilogue splits K/V.
// =========================================================================
#define GSA 40
#define G_STAGES 3
#define G_ASTRIDE (128 * GSA)

struct EpiPlain {};
struct EpiKV {};

template <typename OutT, typename Epi, int NB>
__global__ __launch_bounds__(256, 2) void gemm_f16(const __half* __restrict__ A,
                                                   const __half* __restrict__ B,
                                                   OutT* __restrict__ C,
                                                   void* __restrict__ C2,
                                                   int M, int N, int K) {
    constexpr int BSTRIDE = NB * GSA;
    constexpr int N2T = NB / 32;           // b-ldsm iterations (16 cols each * 2)
    extern __shared__ __align__(16) __half gsm[];
    __half* As = gsm;                       // [3][128*GSA]
    __half* Bs = gsm + G_STAGES * G_ASTRIDE;
    const int tid = threadIdx.x, lane = tid & 31, w = tid >> 5;
    const int bm = blockIdx.y << 7, bn = blockIdx.x * NB;
    const int wm = (w >> 1) << 5, wn = (w & 1) * (NB / 2);

    float acc[2][NB / 16][4];
#pragma unroll
    for (int i = 0; i < 2; i++)
#pragma unroll
        for (int j = 0; j < NB / 16; j++)
#pragma unroll
            for (int k = 0; k < 4; k++) acc[i][j][k] = 0.f;

    const int r = tid >> 2, cch = (tid & 3) << 3;
    const int nt = K >> 5;

    auto load_stage = [&](int t, int s) {
        int k0 = t << 5;
        cpa16(smem_u32(&As[s * G_ASTRIDE + r * GSA + cch]),
              &A[(size_t)(bm + r) * K + k0 + cch]);
        cpa16(smem_u32(&As[s * G_ASTRIDE + (r + 64) * GSA + cch]),
              &A[(size_t)(bm + r + 64) * K + k0 + cch]);
        if constexpr (NB == 128) {
            cpa16(smem_u32(&Bs[s * BSTRIDE + r * GSA + cch]),
                  &B[(size_t)(bn + r) * K + k0 + cch]);
            cpa16(smem_u32(&Bs[s * BSTRIDE + (r + 64) * GSA + cch]),
                  &B[(size_t)(bn + r + 64) * K + k0 + cch]);
        } else {
            cpa16(smem_u32(&Bs[s * BSTRIDE + r * GSA + cch]),
                  &B[(size_t)(bn + r) * K + k0 + cch]);
        }
    };

    load_stage(0, 0); cpa_commit();
    load_stage(1, 1); cpa_commit();

    int s_cur = 0, s_pre = 2;
    for (int t = 0; t < nt; t++) {
        cpa_wait<1>();
        __syncthreads();
        if (t + 2 < nt) load_stage(t + 2, s_pre);
        cpa_commit();

        const __half* as = As + s_cur * G_ASTRIDE;
        const __half* bs = Bs + s_cur * BSTRIDE;
#pragma unroll
        for (int kk = 0; kk < 2; kk++) {
            uint32_t a[2][4];
#pragma unroll
            for (int mt = 0; mt < 2; mt++) {
                uint32_t ad = smem_u32(&as[(wm + mt * 16 + (lane & 15)) * GSA + kk * 16 + ((lane >> 4) << 3)]);
                ldsm4(a[mt][0], a[mt][1], a[mt][2], a[mt][3], ad);
            }
#pragma unroll
            for (int n2 = 0; n2 < N2T; n2++) {
                uint32_t b0, b1, b2, b3;
                uint32_t ad = smem_u32(&bs[(wn + n2 * 16 + ((lane >> 4) << 3) + (lane & 7)) * GSA +
                                           kk * 16 + (((lane >> 3) & 1) << 3)]);
                ldsm4(b0, b1, b2, b3, ad);
#pragma unroll
                for (int mt = 0; mt < 2; mt++) {
                    mma16816(acc[mt][2 * n2],     a[mt][0], a[mt][1], a[mt][2], a[mt][3], b0, b1);
                    mma16816(acc[mt][2 * n2 + 1], a[mt][0], a[mt][1], a[mt][2], a[mt][3], b2, b3);
                }
            }
        }
        s_pre = s_cur;
        s_cur = (s_cur == G_STAGES - 1) ? 0 : s_cur + 1;
    }

    const int g = lane >> 2, c = (lane & 3) << 1;
    if constexpr (__is_same(Epi, EpiKV)) {
        const bool isK = bn < KVDIM;
        const int colbase = bn - (isK ? 0 : KVDIM) + wn;
#pragma unroll
        for (int mt = 0; mt < 2; mt++)
#pragma unroll
            for (int ntl = 0; ntl < NB / 16; ntl++) {
                int row = bm + wm + mt * 16 + g;
                int col = colbase + ntl * 8 + c;
                if (isK) {
                    float* Cp = (float*)C;
                    st2(&Cp[(size_t)row * KVDIM + col],       acc[mt][ntl][0], acc[mt][ntl][1]);
                    st2(&Cp[(size_t)(row + 8) * KVDIM + col], acc[mt][ntl][2], acc[mt][ntl][3]);
                } else {
                    __half* Vp = (__half*)C2;
                    st2(&Vp[(size_t)row * KVDIM + col],       acc[mt][ntl][0], acc[mt][ntl][1]);
                    st2(&Vp[(size_t)(row + 8) * KVDIM + col], acc[mt][ntl][2], acc[mt][ntl][3]);
                }
            }
    } else {
#pragma unroll
        for (int mt = 0; mt < 2; mt++)
#pragma unroll
            for (int ntl = 0; ntl < NB / 16; ntl++) {
                int row = bm + wm + mt * 16 + g;
                int col = bn + wn + ntl * 8 + c;
                st2(&C[(size_t)row * N + col],       acc[mt][ntl][0], acc[mt][ntl][1]);
                st2(&C[(size_t)(row + 8) * N + col], acc[mt][ntl][2], acc[mt][ntl][3]);
            }
    }
}

// ---------------- RMSNorm + RoPE ----------------
__global__ void norm_rope(const float* __restrict__ src, const float* __restrict__ cosp,
                          const float* __restrict__ sinp, const float* __restrict__ wnorm,
                          __half* __restrict__ dst, int nheads, int pos_off, float outscale) {
    const int row = blockIdx.x, h = blockIdx.y, d = threadIdx.x;
    const int stride = nheads * HEAD_DIM;
    const size_t base = (size_t)row * stride + h * HEAD_DIM;
    float x = src[base + d];
    float ss = x * x;
#pragma unroll
    for (int o = 16; o; o >>= 1) ss += __shfl_xor_sync(0xffffffffu, ss, o);
    __shared__ float ws[4];
    const int lane = d & 31, warp = d >> 5;
    if (lane == 0) ws[warp] = ss;
    __syncthreads();
    float sum = ws[0] + ws[1] + ws[2] + ws[3];
    float y = x * rsqrtf(sum * (1.0f / HEAD_DIM) + 1e-6f) * wnorm[d];
    __shared__ float ys[HEAD_DIM];
    ys[d] = y;
    __syncthreads();
    float partner = (d < 64) ? -ys[d + 64] : ys[d - 64];
    int pos = pos_off + row;
    float o = y * cosp[pos * HEAD_DIM + d] + partner * sinp[pos * HEAD_DIM + d];
    dst[base + d] = __float2half(o * outscale);
}

// ---------------- flash attention: f16x2 ex2 softmax, l via ones-MMA ----------------
#define FPAD 136
__global__ __launch_bounds__(256) void flash(const __half* __restrict__ Qh,
                                             const __half* __restrict__ Kh,
                                             const __half* __restrict__ Vh,
                                             __half* __restrict__ Oh) {
    extern __shared__ __align__(16) __half fsm[];
    __half* sK = fsm;
    __half* sV = fsm + 2 * 64 * FPAD;
    const int tid = threadIdx.x, lane = tid & 31, w = tid >> 5;
    const int bx = gridDim.x - 1 - blockIdx.x;
    const int qb = bx << 7;
    const int h = blockIdx.y;
    const int kv = h >> 2;

    {
        const __half* Qp = Qh + (size_t)qb * QKDIM + h * HEAD_DIM;
        for (int i = tid; i < 128 * 16; i += 256) {
            int r = i >> 4, c = (i & 15) << 3;
            *(uint4*)&sK[r * FPAD + c] = *(const uint4*)&Qp[(size_t)r * QKDIM + c];
        }
    }
    __syncthreads();
    uint32_t qa[8][4];
#pragma unroll
    for (int kt = 0; kt < 8; kt++) {
        uint32_t ad = smem_u32(&sK[(w * 16 + (lane & 15)) * FPAD + kt * 16 + ((lane >> 4) << 3)]);
        ldsm4(qa[kt][0], qa[kt][1], qa[kt][2], qa[kt][3], ad);
    }
    __syncthreads();

    float O[16][4];
#pragma unroll
    for (int i = 0; i < 16; i++)
#pragma unroll
        for (int j = 0; j < 4; j++) O[i][j] = 0.f;
    float lacc[4] = {0.f, 0.f, 0.f, 0.f};      // row-sum accumulator (ones-MMA)
    float m0 = -1e30f, m1 = -1e30f;

    const int ntiles = 34 + (bx << 1);
    const __half* Kp = Kh + kv * HEAD_DIM;
    const __half* Vp = Vh + kv * HEAD_DIM;
    const int g = lane >> 2, c2 = (lane & 3) << 1;
    const uint32_t ONE2 = 0x3C003C00u;          // (1.0h, 1.0h)

    auto loadKV = [&](int t, int buf) {
        for (int i = tid; i < 64 * 16; i += 256) {
            int r = i >> 4, c = (i & 15) << 3;
            size_t go = (size_t)(t * 64 + r) * KVDIM + c;
            cpa16(smem_u32(&sK[(buf * 64 + r) * FPAD + c]), &Kp[go]);
            cpa16(smem_u32(&sV[(buf * 64 + r) * FPAD + c]), &Vp[go]);
        }
    };

    loadKV(0, 0);
    cpa_commit();

    for (int t = 0; t < ntiles; t++) {
        if (t + 1 < ntiles) loadKV(t + 1, (t + 1) & 1);
        cpa_commit();
        cpa_wait<1>();
        __syncthreads();
        const int buf = t & 1;
        const int krel0 = t * 64 - (CTXLEN + qb);

        if (krel0 <= w * 16 + 15) {
            float S[8][4];
#pragma unroll
            for (int i = 0; i < 8; i++)
#pragma unroll
                for (int j = 0; j < 4; j++) S[i][j] = 0.f;

#pragma unroll
            for (int kt = 0; kt < 8; kt++) {
#pragma unroll
                for (int n2 = 0; n2 < 4; n2++) {
                    uint32_t b0, b1, b2, b3;
                    uint32_t ad = smem_u32(&sK[(buf * 64 + n2 * 16 + ((lane >> 4) << 3) + (lane & 7)) * FPAD +
                                               kt * 16 + (((lane >> 3) & 1) << 3)]);
                    ldsm4(b0, b1, b2, b3, ad);
                    mma16816(S[2 * n2],     qa[kt][0], qa[kt][1], qa[kt][2], qa[kt][3], b0, b1);
                    mma16816(S[2 * n2 + 1], qa[kt][0], qa[kt][1], qa[kt][2], qa[kt][3], b2, b3);
                }
            }

            if (krel0 + 63 > w * 16) {
                int r0 = w * 16 + g - krel0, r1 = r0 + 8;
#pragma unroll
                for (int ntl = 0; ntl < 8; ntl++) {
                    int col = ntl * 8 + c2;
                    if (col     > r0) S[ntl][0] = -1e30f;
                    if (col + 1 > r0) S[ntl][1] = -1e30f;
                    if (col     > r1) S[ntl][2] = -1e30f;
                    if (col + 1 > r1) S[ntl][3] = -1e30f;
                }
            }

            // row max (fp32) + 2-level shfl
            float mt0 = -1e30f, mt1 = -1e30f;
#pragma unroll
            for (int ntl = 0; ntl < 8; ntl++) {
                mt0 = fmaxf(mt0, fmaxf(S[ntl][0], S[ntl][1]));
                mt1 = fmaxf(mt1, fmaxf(S[ntl][2], S[ntl][3]));
            }
            mt0 = fmaxf(mt0, __shfl_xor_sync(0xffffffffu, mt0, 1));
            mt0 = fmaxf(mt0, __shfl_xor_sync(0xffffffffu, mt0, 2));
            mt1 = fmaxf(mt1, __shfl_xor_sync(0xffffffffu, mt1, 1));
            mt1 = fmaxf(mt1, __shfl_xor_sync(0xffffffffu, mt1, 2));
            float mn0 = fmaxf(m0, mt0), mn1 = fmaxf(m1, mt1);

            // P = exp2(S - mn) computed as fp16 pairs (A-fragment ready)
            uint32_t P[8][2];
#pragma unroll
            for (int ntl = 0; ntl < 8; ntl++) {
                P[ntl][0] = h2exp2(packh2(S[ntl][0] - mn0, S[ntl][1] - mn0));
                P[ntl][1] = h2exp2(packh2(S[ntl][2] - mn1, S[ntl][3] - mn1));
            }

            if (mn0 > m0 || mn1 > m1) {
                float a0 = exp2f(m0 - mn0), a1 = exp2f(m1 - mn1);
                lacc[0] *= a0; lacc[1] *= a0; lacc[2] *= a1; lacc[3] *= a1;
#pragma unroll
                for (int ntl = 0; ntl < 16; ntl++) {
                    O[ntl][0] *= a0; O[ntl][1] *= a0; O[ntl][2] *= a1; O[ntl][3] *= a1;
                }
            }
            m0 = mn0; m1 = mn1;

            // P @ V, plus l += P @ ones
#pragma unroll
            for (int kc = 0; kc < 4; kc++) {
                uint32_t A0 = P[2 * kc][0],     A1 = P[2 * kc][1];
                uint32_t A2 = P[2 * kc + 1][0], A3 = P[2 * kc + 1][1];
                mma16816(lacc, A0, A1, A2, A3, ONE2, ONE2);
#pragma unroll
                for (int d2 = 0; d2 < 8; d2++) {
                    uint32_t v0, v1, v2, v3;
                    uint32_t ad = smem_u32(&sV[(buf * 64 + kc * 16 + (lane & 15)) * FPAD +
                                               d2 * 16 + ((lane >> 4) << 3)]);
                    ldsm4t(v0, v1, v2, v3, ad);
                    mma16816(O[2 * d2],     A0, A1, A2, A3, v0, v1);
                    mma16816(O[2 * d2 + 1], A0, A1, A2, A3, v2, v3);
                }
            }
        }
        __syncthreads();
    }

    float i0 = 1.f / lacc[0], i1 = 1.f / lacc[2];
    __half* Op = Oh + (size_t)(qb + w * 16) * QKDIM + h * HEAD_DIM;
#pragma unroll
    for (int ntl = 0; ntl < 16; ntl++) {
        int col = ntl * 8 + c2;
        *(__half2*)&Op[(size_t)g * QKDIM + col]       = __floats2half2_rn(O[ntl][0] * i0, O[ntl][1] * i0);
        *(__half2*)&Op[(size_t)(g + 8) * QKDIM + col] = __floats2half2_rn(O[ntl][2] * i1, O[ntl][3] * i1);
    }
}

// ---------------- launcher ----------------
#define G_SMEM_NB(NB) (G_STAGES * (128 + (NB)) * GSA * 2)
extern "C" void kernel_launch(void* const* d_in, const int* in_sizes, int n_in,
                              void* d_out, int out_size) {
    const float* hidden = (const float*)d_in[0];
    const float* target = (const float*)d_in[1];
    const float* cosp   = (const float*)d_in[2];
    const float* sinp   = (const float*)d_in[3];
    const float* wq = (const float*)d_in[5];
    const float* wk = (const float*)d_in[6];
    const float* wv = (const float*)d_in[7];
    const float* wo = (const float*)d_in[8];
    const float* qw = (const float*)d_in[9];
    const float* kw = (const float*)d_in[10];
    float* out = (float*)d_out;

    __half *Xh, *Wqh, *Wkvh, *Woh, *Qh, *Kh, *Vh, *Oh;
    float *Qraw, *Kraw;
    cudaGetSymbolAddress((void**)&Xh, g_Xh);
    cudaGetSymbolAddress((void**)&Wqh, g_Wqh);
    cudaGetSymbolAddress((void**)&Wkvh, g_Wkvh);
    cudaGetSymbolAddress((void**)&Woh, g_Woh);
    cudaGetSymbolAddress((void**)&Qraw, g_Qraw);
    cudaGetSymbolAddress((void**)&Kraw, g_Kraw);
    cudaGetSymbolAddress((void**)&Qh, g_Qh);
    cudaGetSymbolAddress((void**)&Kh, g_Kh);
    cudaGetSymbolAddress((void**)&Vh, g_Vh);
    cudaGetSymbolAddress((void**)&Oh, g_Oh);

    cudaFuncSetAttribute((const void*)gemm_f16<float, EpiPlain, 128>,
                         cudaFuncAttributeMaxDynamicSharedMemorySize, G_SMEM_NB(128));
    cudaFuncSetAttribute((const void*)gemm_f16<float, EpiKV, 128>,
                         cudaFuncAttributeMaxDynamicSharedMemorySize, G_SMEM_NB(128));
    cudaFuncSetAttribute((const void*)gemm_f16<float, EpiPlain, 64>,
                         cudaFuncAttributeMaxDynamicSharedMemorySize, G_SMEM_NB(64));
    cudaFuncSetAttribute((const void*)flash,
                         cudaFuncAttributeMaxDynamicSharedMemorySize, 4 * 64 * FPAD * 2);

    cvt3<<<1024, 256>>>(target, Xh, CTXLEN * HIDDEN / 4,
                        hidden, Xh + (size_t)CTXLEN * HIDDEN, QLEN * HIDDEN / 4,
                        wq, Wqh, QKDIM * HIDDEN / 4);
    cvt3<<<1024, 256>>>(wk, Wkvh, KVDIM * HIDDEN / 4,
                        wv, Wkvh + (size_t)KVDIM * HIDDEN, KVDIM * HIDDEN / 4,
                        wo, Woh, HIDDEN * QKDIM / 4);

    gemm_f16<float, EpiPlain, 128><<<dim3(QKDIM / 128, QLEN / 128), 256, G_SMEM_NB(128)>>>(
        Xh + (size_t)CTXLEN * HIDDEN, Wqh, Qraw, nullptr, QLEN, QKDIM, HIDDEN);
    gemm_f16<float, EpiKV, 128><<<dim3(2 * KVDIM / 128, TLEN / 128), 256, G_SMEM_NB(128)>>>(
        Xh, Wkvh, Kraw, Vh, TLEN, 2 * KVDIM, HIDDEN);

    norm_rope<<<dim3(QLEN, H_HEADS), 128>>>(Qraw, cosp, sinp, qw, Qh, H_HEADS, CTXLEN,
                                            0.08838834764831845f * 1.4426950408889634f);
    norm_rope<<<dim3(TLEN, KV_HEADS), 128>>>(Kraw, cosp, sinp, kw, Kh, KV_HEADS, 0, 1.0f);

    flash<<<dim3(QLEN / 128, H_HEADS), 256, 4 * 64 * FPAD * 2>>>(Qh, Kh, Vh, Oh);

    // O projection: BN=64 doubles the grid (256 CTAs) to fix the tail
    gemm_f16<float, EpiPlain, 64><<<dim3(HIDDEN / 64, QLEN / 128), 256, G_SMEM_NB(64)>>>(
        Oh, Woh, out, nullptr, QLEN, HIDDEN, QKDIM);
}

// round 8
// speedup vs baseline: 1.2541x; 1.0184x over previous
#include <cuda_runtime.h>
#include <cuda_fp16.h>
#include <cstdint>

#define H_HEADS   32
#define KV_HEADS  8
#define HEAD_DIM  128
#define HIDDEN    2048
#define QLEN      1024
#define CTXLEN    2048
#define TLEN      3072
#define QKDIM     (H_HEADS * HEAD_DIM)    // 4096
#define KVDIM     (KV_HEADS * HEAD_DIM)   // 1024

// ---------------- scratch ----------------
__device__ __half g_Xh  [TLEN * HIDDEN];
__device__ __half g_Wqh [QKDIM * HIDDEN];
__device__ __half g_Wkvh[2 * KVDIM * HIDDEN];
__device__ __half g_Woh [HIDDEN * QKDIM];
__device__ float  g_Qraw[QLEN * QKDIM];
__device__ float  g_Kraw[TLEN * KVDIM];
__device__ __half g_Qh  [QLEN * QKDIM];
__device__ __half g_Kh  [TLEN * KVDIM];
__device__ __half g_Vh  [TLEN * KVDIM];
__device__ __half g_Oh  [QLEN * QKDIM];

// ---------------- helpers ----------------
__device__ __forceinline__ uint32_t smem_u32(const void* p) {
    return (uint32_t)__cvta_generic_to_shared(p);
}
__device__ __forceinline__ void ldsm4(uint32_t& r0, uint32_t& r1, uint32_t& r2, uint32_t& r3, uint32_t a) {
    asm volatile("ldmatrix.sync.aligned.m8n8.x4.shared.b16 {%0,%1,%2,%3},[%4];\n"
                 : "=r"(r0), "=r"(r1), "=r"(r2), "=r"(r3) : "r"(a));
}
__device__ __forceinline__ void ldsm4t(uint32_t& r0, uint32_t& r1, uint32_t& r2, uint32_t& r3, uint32_t a) {
    asm volatile("ldmatrix.sync.aligned.m8n8.x4.trans.shared.b16 {%0,%1,%2,%3},[%4];\n"
                 : "=r"(r0), "=r"(r1), "=r"(r2), "=r"(r3) : "r"(a));
}
__device__ __forceinline__ void mma16816(float* c, uint32_t a0, uint32_t a1, uint32_t a2, uint32_t a3,
                                         uint32_t b0, uint32_t b1) {
    asm volatile("mma.sync.aligned.m16n8k16.row.col.f32.f16.f16.f32 "
                 "{%0,%1,%2,%3},{%4,%5,%6,%7},{%8,%9},{%0,%1,%2,%3};\n"
                 : "+f"(c[0]), "+f"(c[1]), "+f"(c[2]), "+f"(c[3])
                 : "r"(a0), "r"(a1), "r"(a2), "r"(a3), "r"(b0), "r"(b1));
}
__device__ __forceinline__ uint32_t packh2(float a, float b) {
    __half2 h = __floats2half2_rn(a, b);
    return *reinterpret_cast<uint32_t*>(&h);
}
__device__ __forceinline__ uint32_t h2exp2(uint32_t x) {
    uint32_t r;
    asm("ex2.approx.f16x2 %0, %1;" : "=r"(r) : "r"(x));
    return r;
}
__device__ __forceinline__ void cpa16(uint32_t dst, const void* src) {
    asm volatile("cp.async.cg.shared.global [%0],[%1],16;\n" :: "r"(dst), "l"(src));
}
__device__ __forceinline__ void cpa_commit() { asm volatile("cp.async.commit_group;\n"); }
template <int N> __device__ __forceinline__ void cpa_wait() {
    asm volatile("cp.async.wait_group %0;\n" :: "n"(N));
}
__device__ __forceinline__ void st2(float* p, float a, float b) { *(float2*)p = make_float2(a, b); }
__device__ __forceinline__ void st2(__half* p, float a, float b) { *(__half2*)p = __floats2half2_rn(a, b); }

// ---------------- fused fp32 -> fp16 conversion: 6 segments, 2x float4/thread ------
__global__ void cvt6(const float* s0, __half* d0, int n0, const float* s1, __half* d1, int n1,
                     const float* s2, __half* d2, int n2, const float* s3, __half* d3, int n3,
                     const float* s4, __half* d4, int n4c, const float* s5, __half* d5, int n5) {
    // counts are in units of 2 float4 (8 floats)
    int total = n0 + n1 + n2 + n3 + n4c + n5;
    int stride = gridDim.x * blockDim.x;
    for (int i = blockIdx.x * blockDim.x + threadIdx.x; i < total; i += stride) {
        const float* s; __half* d; int j = i;
        if (j < n0) { s = s0; d = d0; }
        else if ((j -= n0) < n1) { s = s1; d = d1; }
        else if ((j -= n1) < n2) { s = s2; d = d2; }
        else if ((j -= n2) < n3) { s = s3; d = d3; }
        else if ((j -= n3) < n4c) { s = s4; d = d4; }
        else { j -= n4c; s = s5; d = d5; }
        float4 a = reinterpret_cast<const float4*>(s)[2 * j];
        float4 b = reinterpret_cast<const float4*>(s)[2 * j + 1];
        __half2 h0 = __floats2half2_rn(a.x, a.y), h1 = __floats2half2_rn(a.z, a.w);
        __half2 h2 = __floats2half2_rn(b.x, b.y), h3 = __floats2half2_rn(b.z, b.w);
        uint4 o;
        o.x = *(uint32_t*)&h0; o.y = *(uint32_t*)&h1; o.z = *(uint32_t*)&h2; o.w = *(uint32_t*)&h3;
        reinterpret_cast<uint4*>(d)[j] = o;
    }
}

// =========================================================================
// Merged Q+KV projection: one launch, 640 CTAs.
//   bid <  256: Q  = hidden @ Wq^T   -> Qraw fp32 [1024 x 4096]
//   bid >= 256: KV = X @ Wkv^T       -> Kraw fp32 / Vh fp16 [3072 x 1024 each]
// 128x128x32 tile, 256 thr, 3-stage cp.async, one sync per k-iter.
// =========================================================================
#define GSA 40
#define G_STAGES 3
#define G_ASTRIDE (128 * GSA)
#define G_SMEM128 (G_STAGES * G_ASTRIDE * 2 * 2)

__global__ __launch_bounds__(256, 2) void gemm_qkv(const __half* __restrict__ Xh,
                                                   const __half* __restrict__ Wqh,
                                                   const __half* __restrict__ Wkvh,
                                                   float* __restrict__ Qraw,
                                                   float* __restrict__ Kraw,
                                                   __half* __restrict__ Vh) {
    extern __shared__ __align__(16) __half gsm[];
    __half* As = gsm;
    __half* Bs = gsm + G_STAGES * G_ASTRIDE;
    const int tid = threadIdx.x, lane = tid & 31, w = tid >> 5;
    const int bid = blockIdx.x;
    const bool isQ = bid < 256;
    const __half* A;
    const __half* B;
    int bm, bn;
    if (isQ) {
        A = Xh + (size_t)CTXLEN * HIDDEN;
        B = Wqh;
        bm = (bid >> 5) << 7;     // 8 row tiles
        bn = (bid & 31) << 7;     // 32 col tiles
    } else {
        int b = bid - 256;
        A = Xh;
        B = Wkvh;
        bm = (b >> 4) << 7;       // 24 row tiles
        bn = (b & 15) << 7;       // 16 col tiles
    }
    const int wm = (w >> 1) << 5, wn = (w & 1) << 6;
    constexpr int K = HIDDEN;

    float acc[2][8][4];
#pragma unroll
    for (int i = 0; i < 2; i++)
#pragma unroll
        for (int j = 0; j < 8; j++)
#pragma unroll
            for (int k = 0; k < 4; k++) acc[i][j][k] = 0.f;

    const int r = tid >> 2, cch = (tid & 3) << 3;
    const int nt = K >> 5;

    auto load_stage = [&](int t, int s) {
        int k0 = t << 5;
        cpa16(smem_u32(&As[s * G_ASTRIDE + r * GSA + cch]),        &A[(size_t)(bm + r) * K + k0 + cch]);
        cpa16(smem_u32(&As[s * G_ASTRIDE + (r + 64) * GSA + cch]), &A[(size_t)(bm + r + 64) * K + k0 + cch]);
        cpa16(smem_u32(&Bs[s * G_ASTRIDE + r * GSA + cch]),        &B[(size_t)(bn + r) * K + k0 + cch]);
        cpa16(smem_u32(&Bs[s * G_ASTRIDE + (r + 64) * GSA + cch]), &B[(size_t)(bn + r + 64) * K + k0 + cch]);
    };

    load_stage(0, 0); cpa_commit();
    load_stage(1, 1); cpa_commit();

    int s_cur = 0, s_pre = 2;
    for (int t = 0; t < nt; t++) {
        cpa_wait<1>();
        __syncthreads();
        if (t + 2 < nt) load_stage(t + 2, s_pre);
        cpa_commit();

        const __half* as = As + s_cur * G_ASTRIDE;
        const __half* bs = Bs + s_cur * G_ASTRIDE;
#pragma unroll
        for (int kk = 0; kk < 2; kk++) {
            uint32_t a[2][4];
#pragma unroll
            for (int mt = 0; mt < 2; mt++) {
                uint32_t ad = smem_u32(&as[(wm + mt * 16 + (lane & 15)) * GSA + kk * 16 + ((lane >> 4) << 3)]);
                ldsm4(a[mt][0], a[mt][1], a[mt][2], a[mt][3], ad);
            }
#pragma unroll
            for (int n2 = 0; n2 < 4; n2++) {
                uint32_t b0, b1, b2, b3;
                uint32_t ad = smem_u32(&bs[(wn + n2 * 16 + ((lane >> 4) << 3) + (lane & 7)) * GSA +
                                           kk * 16 + (((lane >> 3) & 1) << 3)]);
                ldsm4(b0, b1, b2, b3, ad);
#pragma unroll
                for (int mt = 0; mt < 2; mt++) {
                    mma16816(acc[mt][2 * n2],     a[mt][0], a[mt][1], a[mt][2], a[mt][3], b0, b1);
                    mma16816(acc[mt][2 * n2 + 1], a[mt][0], a[mt][1], a[mt][2], a[mt][3], b2, b3);
                }
            }
        }
        s_pre = s_cur;
        s_cur = (s_cur == G_STAGES - 1) ? 0 : s_cur + 1;
    }

    const int g = lane >> 2, c = (lane & 3) << 1;
    if (isQ) {
#pragma unroll
        for (int mt = 0; mt < 2; mt++)
#pragma unroll
            for (int ntl = 0; ntl < 8; ntl++) {
                int row = bm + wm + mt * 16 + g;
                int col = bn + wn + ntl * 8 + c;
                st2(&Qraw[(size_t)row * QKDIM + col],       acc[mt][ntl][0], acc[mt][ntl][1]);
                st2(&Qraw[(size_t)(row + 8) * QKDIM + col], acc[mt][ntl][2], acc[mt][ntl][3]);
            }
    } else {
        const bool isK = bn < KVDIM;
        const int colbase = bn - (isK ? 0 : KVDIM) + wn;
#pragma unroll
        for (int mt = 0; mt < 2; mt++)
#pragma unroll
            for (int ntl = 0; ntl < 8; ntl++) {
                int row = bm + wm + mt * 16 + g;
                int col = colbase + ntl * 8 + c;
                if (isK) {
                    st2(&Kraw[(size_t)row * KVDIM + col],       acc[mt][ntl][0], acc[mt][ntl][1]);
                    st2(&Kraw[(size_t)(row + 8) * KVDIM + col], acc[mt][ntl][2], acc[mt][ntl][3]);
                } else {
                    st2(&Vh[(size_t)row * KVDIM + col],       acc[mt][ntl][0], acc[mt][ntl][1]);
                    st2(&Vh[(size_t)(row + 8) * KVDIM + col], acc[mt][ntl][2], acc[mt][ntl][3]);
                }
            }
    }
}

// ---------------- O-projection GEMM (BN=64 for grid size) ----------------
#define GO_SMEM (G_STAGES * (128 + 64) * GSA * 2)
__global__ __launch_bounds__(256, 2) void gemm_o(const __half* __restrict__ A,
                                                 const __half* __restrict__ B,
                                                 float* __restrict__ C) {
    constexpr int NB = 64, BSTRIDE = NB * GSA, K = QKDIM, N = HIDDEN;
    extern __shared__ __align__(16) __half gsm[];
    __half* As = gsm;
    __half* Bs = gsm + G_STAGES * G_ASTRIDE;
    const int tid = threadIdx.x, lane = tid & 31, w = tid >> 5;
    const int bm = blockIdx.y << 7, bn = blockIdx.x * NB;
    const int wm = (w >> 1) << 5, wn = (w & 1) << 5;

    float acc[2][4][4];
#pragma unroll
    for (int i = 0; i < 2; i++)
#pragma unroll
        for (int j = 0; j < 4; j++)
#pragma unroll
            for (int k = 0; k < 4; k++) acc[i][j][k] = 0.f;

    const int r = tid >> 2, cch = (tid & 3) << 3;
    const int nt = K >> 5;

    auto load_stage = [&](int t, int s) {
        int k0 = t << 5;
        cpa16(smem_u32(&As[s * G_ASTRIDE + r * GSA + cch]),        &A[(size_t)(bm + r) * K + k0 + cch]);
        cpa16(smem_u32(&As[s * G_ASTRIDE + (r + 64) * GSA + cch]), &A[(size_t)(bm + r + 64) * K + k0 + cch]);
        cpa16(smem_u32(&Bs[s * BSTRIDE + r * GSA + cch]),          &B[(size_t)(bn + r) * K + k0 + cch]);
    };

    load_stage(0, 0); cpa_commit();
    load_stage(1, 1); cpa_commit();

    int s_cur = 0, s_pre = 2;
    for (int t = 0; t < nt; t++) {
        cpa_wait<1>();
        __syncthreads();
        if (t + 2 < nt) load_stage(t + 2, s_pre);
        cpa_commit();

        const __half* as = As + s_cur * G_ASTRIDE;
        const __half* bs = Bs + s_cur * BSTRIDE;
#pragma unroll
        for (int kk = 0; kk < 2; kk++) {
            uint32_t a[2][4];
#pragma unroll
            for (int mt = 0; mt < 2; mt++) {
                uint32_t ad = smem_u32(&as[(wm + mt * 16 + (lane & 15)) * GSA + kk * 16 + ((lane >> 4) << 3)]);
                ldsm4(a[mt][0], a[mt][1], a[mt][2], a[mt][3], ad);
            }
#pragma unroll
            for (int n2 = 0; n2 < 2; n2++) {
                uint32_t b0, b1, b2, b3;
                uint32_t ad = smem_u32(&bs[(wn + n2 * 16 + ((lane >> 4) << 3) + (lane & 7)) * GSA +
                                           kk * 16 + (((lane >> 3) & 1) << 3)]);
                ldsm4(b0, b1, b2, b3, ad);
#pragma unroll
                for (int mt = 0; mt < 2; mt++) {
                    mma16816(acc[mt][2 * n2],     a[mt][0], a[mt][1], a[mt][2], a[mt][3], b0, b1);
                    mma16816(acc[mt][2 * n2 + 1], a[mt][0], a[mt][1], a[mt][2], a[mt][3], b2, b3);
                }
            }
        }
        s_pre = s_cur;
        s_cur = (s_cur == G_STAGES - 1) ? 0 : s_cur + 1;
    }

    const int g = lane >> 2, c = (lane & 3) << 1;
#pragma unroll
    for (int mt = 0; mt < 2; mt++)
#pragma unroll
        for (int ntl = 0; ntl < 4; ntl++) {
            int row = bm + wm + mt * 16 + g;
            int col = bn + wn + ntl * 8 + c;
            st2(&C[(size_t)row * N + col],       acc[mt][ntl][0], acc[mt][ntl][1]);
            st2(&C[(size_t)(row + 8) * N + col], acc[mt][ntl][2], acc[mt][ntl][3]);
        }
}

// ---------------- merged RMSNorm + RoPE (Q and K in one launch) ----------------
__global__ void norm_rope2(const float* __restrict__ Qraw, const float* __restrict__ Kraw,
                           const float* __restrict__ cosp, const float* __restrict__ sinp,
                           const float* __restrict__ qw, const float* __restrict__ kw,
                           __half* __restrict__ Qh, __half* __restrict__ Kh) {
    const int bid = blockIdx.x, d = threadIdx.x;
    const float* src; const float* wnorm; __half* dst;
    int row, h, nheads, pos;
    float outscale;
    if (bid < QLEN * H_HEADS) {
        row = bid >> 5; h = bid & 31; nheads = H_HEADS;
        src = Qraw; wnorm = qw; dst = Qh;
        pos = CTXLEN + row;
        outscale = 0.08838834764831845f * 1.4426950408889634f;
    } else {
        int b = bid - QLEN * H_HEADS;
        row = b >> 3; h = b & 7; nheads = KV_HEADS;
        src = Kraw; wnorm = kw; dst = Kh;
        pos = row;
        outscale = 1.0f;
    }
    const size_t base = (size_t)row * nheads * HEAD_DIM + h * HEAD_DIM;
    float x = src[base + d];
    float ss = x * x;
#pragma unroll
    for (int o = 16; o; o >>= 1) ss += __shfl_xor_sync(0xffffffffu, ss, o);
    __shared__ float ws[4];
    const int lane = d & 31, warp = d >> 5;
    if (lane == 0) ws[warp] = ss;
    __syncthreads();
    float sum = ws[0] + ws[1] + ws[2] + ws[3];
    float y = x * rsqrtf(sum * (1.0f / HEAD_DIM) + 1e-6f) * wnorm[d];
    __shared__ float ys[HEAD_DIM];
    ys[d] = y;
    __syncthreads();
    float partner = (d < 64) ? -ys[d + 64] : ys[d - 64];
    float o = y * cosp[pos * HEAD_DIM + d] + partner * sinp[pos * HEAD_DIM + d];
    dst[base + d] = __float2half(o * outscale);
}

// ---------------- flash attention (round-7 version) ----------------
#define FPAD 136
__global__ __launch_bounds__(256) void flash(const __half* __restrict__ Qh,
                                             const __half* __restrict__ Kh,
                                             const __half* __restrict__ Vh,
                                             __half* __restrict__ Oh) {
    extern __shared__ __align__(16) __half fsm[];
    __half* sK = fsm;
    __half* sV = fsm + 2 * 64 * FPAD;
    const int tid = threadIdx.x, lane = tid & 31, w = tid >> 5;
    const int bx = gridDim.x - 1 - blockIdx.x;
    const int qb = bx << 7;
    const int h = blockIdx.y;
    const int kv = h >> 2;

    {
        const __half* Qp = Qh + (size_t)qb * QKDIM + h * HEAD_DIM;
        for (int i = tid; i < 128 * 16; i += 256) {
            int r = i >> 4, c = (i & 15) << 3;
            *(uint4*)&sK[r * FPAD + c] = *(const uint4*)&Qp[(size_t)r * QKDIM + c];
        }
    }
    __syncthreads();
    uint32_t qa[8][4];
#pragma unroll
    for (int kt = 0; kt < 8; kt++) {
        uint32_t ad = smem_u32(&sK[(w * 16 + (lane & 15)) * FPAD + kt * 16 + ((lane >> 4) << 3)]);
        ldsm4(qa[kt][0], qa[kt][1], qa[kt][2], qa[kt][3], ad);
    }
    __syncthreads();

    float O[16][4];
#pragma unroll
    for (int i = 0; i < 16; i++)
#pragma unroll
        for (int j = 0; j < 4; j++) O[i][j] = 0.f;
    float lacc[4] = {0.f, 0.f, 0.f, 0.f};
    float m0 = -1e30f, m1 = -1e30f;

    const int ntiles = 34 + (bx << 1);
    const __half* Kp = Kh + kv * HEAD_DIM;
    const __half* Vp = Vh + kv * HEAD_DIM;
    const int g = lane >> 2, c2 = (lane & 3) << 1;
    const uint32_t ONE2 = 0x3C003C00u;

    auto loadKV = [&](int t, int buf) {
        for (int i = tid; i < 64 * 16; i += 256) {
            int r = i >> 4, c = (i & 15) << 3;
            size_t go = (size_t)(t * 64 + r) * KVDIM + c;
            cpa16(smem_u32(&sK[(buf * 64 + r) * FPAD + c]), &Kp[go]);
            cpa16(smem_u32(&sV[(buf * 64 + r) * FPAD + c]), &Vp[go]);
        }
    };

    loadKV(0, 0);
    cpa_commit();

    for (int t = 0; t < ntiles; t++) {
        if (t + 1 < ntiles) loadKV(t + 1, (t + 1) & 1);
        cpa_commit();
        cpa_wait<1>();
        __syncthreads();
        const int buf = t & 1;
        const int krel0 = t * 64 - (CTXLEN + qb);

        if (krel0 <= w * 16 + 15) {
            float S[8][4];
#pragma unroll
            for (int i = 0; i < 8; i++)
#pragma unroll
                for (int j = 0; j < 4; j++) S[i][j] = 0.f;

#pragma unroll
            for (int kt = 0; kt < 8; kt++) {
#pragma unroll
                for (int n2 = 0; n2 < 4; n2++) {
                    uint32_t b0, b1, b2, b3;
                    uint32_t ad = smem_u32(&sK[(buf * 64 + n2 * 16 + ((lane >> 4) << 3) + (lane & 7)) * FPAD +
                                               kt * 16 + (((lane >> 3) & 1) << 3)]);
                    ldsm4(b0, b1, b2, b3, ad);
                    mma16816(S[2 * n2],     qa[kt][0], qa[kt][1], qa[kt][2], qa[kt][3], b0, b1);
                    mma16816(S[2 * n2 + 1], qa[kt][0], qa[kt][1], qa[kt][2], qa[kt][3], b2, b3);
                }
            }

            if (krel0 + 63 > w * 16) {
                int r0 = w * 16 + g - krel0, r1 = r0 + 8;
#pragma unroll
                for (int ntl = 0; ntl < 8; ntl++) {
                    int col = ntl * 8 + c2;
                    if (col     > r0) S[ntl][0] = -1e30f;
                    if (col + 1 > r0) S[ntl][1] = -1e30f;
                    if (col     > r1) S[ntl][2] = -1e30f;
                    if (col + 1 > r1) S[ntl][3] = -1e30f;
                }
            }

            float mt0 = -1e30f, mt1 = -1e30f;
#pragma unroll
            for (int ntl = 0; ntl < 8; ntl++) {
                mt0 = fmaxf(mt0, fmaxf(S[ntl][0], S[ntl][1]));
                mt1 = fmaxf(mt1, fmaxf(S[ntl][2], S[ntl][3]));
            }
            mt0 = fmaxf(mt0, __shfl_xor_sync(0xffffffffu, mt0, 1));
            mt0 = fmaxf(mt0, __shfl_xor_sync(0xffffffffu, mt0, 2));
            mt1 = fmaxf(mt1, __shfl_xor_sync(0xffffffffu, mt1, 1));
            mt1 = fmaxf(mt1, __shfl_xor_sync(0xffffffffu, mt1, 2));
            float mn0 = fmaxf(m0, mt0), mn1 = fmaxf(m1, mt1);

            uint32_t P[8][2];
#pragma unroll
            for (int ntl = 0; ntl < 8; ntl++) {
                P[ntl][0] = h2exp2(packh2(S[ntl][0] - mn0, S[ntl][1] - mn0));
                P[ntl][1] = h2exp2(packh2(S[ntl][2] - mn1, S[ntl][3] - mn1));
            }

            if (mn0 > m0 || mn1 > m1) {
                float a0 = exp2f(m0 - mn0), a1 = exp2f(m1 - mn1);
                lacc[0] *= a0; lacc[1] *= a0; lacc[2] *= a1; lacc[3] *= a1;
#pragma unroll
                for (int ntl = 0; ntl < 16; ntl++) {
                    O[ntl][0] *= a0; O[ntl][1] *= a0; O[ntl][2] *= a1; O[ntl][3] *= a1;
                }
            }
            m0 = mn0; m1 = mn1;

#pragma unroll
            for (int kc = 0; kc < 4; kc++) {
                uint32_t A0 = P[2 * kc][0],     A1 = P[2 * kc][1];
                uint32_t A2 = P[2 * kc + 1][0], A3 = P[2 * kc + 1][1];
                mma16816(lacc, A0, A1, A2, A3, ONE2, ONE2);
#pragma unroll
                for (int d2 = 0; d2 < 8; d2++) {
                    uint32_t v0, v1, v2, v3;
                    uint32_t ad = smem_u32(&sV[(buf * 64 + kc * 16 + (lane & 15)) * FPAD +
                                               d2 * 16 + ((lane >> 4) << 3)]);
                    ldsm4t(v0, v1, v2, v3, ad);
                    mma16816(O[2 * d2],     A0, A1, A2, A3, v0, v1);
                    mma16816(O[2 * d2 + 1], A0, A1, A2, A3, v2, v3);
                }
            }
        }
        __syncthreads();
    }

    float i0 = 1.f / lacc[0], i1 = 1.f / lacc[2];
    __half* Op = Oh + (size_t)(qb + w * 16) * QKDIM + h * HEAD_DIM;
#pragma unroll
    for (int ntl = 0; ntl < 16; ntl++) {
        int col = ntl * 8 + c2;
        *(__half2*)&Op[(size_t)g * QKDIM + col]       = __floats2half2_rn(O[ntl][0] * i0, O[ntl][1] * i0);
        *(__half2*)&Op[(size_t)(g + 8) * QKDIM + col] = __floats2half2_rn(O[ntl][2] * i1, O[ntl][3] * i1);
    }
}

// ---------------- launcher ----------------
extern "C" void kernel_launch(void* const* d_in, const int* in_sizes, int n_in,
                              void* d_out, int out_size) {
    const float* hidden = (const float*)d_in[0];
    const float* target = (const float*)d_in[1];
    const float* cosp   = (const float*)d_in[2];
    const float* sinp   = (const float*)d_in[3];
    const float* wq = (const float*)d_in[5];
    const float* wk = (const float*)d_in[6];
    const float* wv = (const float*)d_in[7];
    const float* wo = (const float*)d_in[8];
    const float* qw = (const float*)d_in[9];
    const float* kw = (const float*)d_in[10];
    float* out = (float*)d_out;

    __half *Xh, *Wqh, *Wkvh, *Woh, *Qh, *Kh, *Vh, *Oh;
    float *Qraw, *Kraw;
    cudaGetSymbolAddress((void**)&Xh, g_Xh);
    cudaGetSymbolAddress((void**)&Wqh, g_Wqh);
    cudaGetSymbolAddress((void**)&Wkvh, g_Wkvh);
    cudaGetSymbolAddress((void**)&Woh, g_Woh);
    cudaGetSymbolAddress((void**)&Qraw, g_Qraw);
    cudaGetSymbolAddress((void**)&Kraw, g_Kraw);
    cudaGetSymbolAddress((void**)&Qh, g_Qh);
    cudaGetSymbolAddress((void**)&Kh, g_Kh);
    cudaGetSymbolAddress((void**)&Vh, g_Vh);
    cudaGetSymbolAddress((void**)&Oh, g_Oh);

    cudaFuncSetAttribute((const void*)gemm_qkv, cudaFuncAttributeMaxDynamicSharedMemorySize, G_SMEM128);
    cudaFuncSetAttribute((const void*)gemm_o,   cudaFuncAttributeMaxDynamicSharedMemorySize, GO_SMEM);
    cudaFuncSetAttribute((const void*)flash,    cudaFuncAttributeMaxDynamicSharedMemorySize, 4 * 64 * FPAD * 2);

    // one fused conversion launch (counts in 8-float units)
    cvt6<<<1184, 256>>>(target, Xh, CTXLEN * HIDDEN / 8,
                        hidden, Xh + (size_t)CTXLEN * HIDDEN, QLEN * HIDDEN / 8,
                        wq, Wqh, QKDIM * HIDDEN / 8,
                        wk, Wkvh, KVDIM * HIDDEN / 8,
                        wv, Wkvh + (size_t)KVDIM * HIDDEN, KVDIM * HIDDEN / 8,
                        wo, Woh, HIDDEN * QKDIM / 8);

    // merged Q + KV projections: 640 CTAs in one launch
    gemm_qkv<<<640, 256, G_SMEM128>>>(Xh, Wqh, Wkvh, Qraw, Kraw, Vh);

    // merged norm+rope
    norm_rope2<<<QLEN * H_HEADS + TLEN * KV_HEADS, 128>>>(Qraw, Kraw, cosp, sinp, qw, kw, Qh, Kh);

    flash<<<dim3(QLEN / 128, H_HEADS), 256, 4 * 64 * FPAD * 2>>>(Qh, Kh, Vh, Oh);

    gemm_o<<<dim3(HIDDEN / 64, QLEN / 128), 256, GO_SMEM>>>(Oh, Woh, out);
}

// round 9
// speedup vs baseline: 1.2973x; 1.0344x over previous
#include <cuda_runtime.h>
#include <cuda_fp16.h>
#include <cstdint>

#define H_HEADS   32
#define KV_HEADS  8
#define HEAD_DIM  128
#define HIDDEN    2048
#define QLEN      1024
#define CTXLEN    2048
#define TLEN      3072
#define QKDIM     (H_HEADS * HEAD_DIM)    // 4096
#define KVDIM     (KV_HEADS * HEAD_DIM)   // 1024

// ---------------- scratch ----------------
__device__ __half g_Xh  [TLEN * HIDDEN];
__device__ __half g_Wqh [QKDIM * HIDDEN];
__device__ __half g_Wkvh[2 * KVDIM * HIDDEN];
__device__ __half g_Woh [HIDDEN * QKDIM];
__device__ float  g_Qraw[QLEN * QKDIM];
__device__ float  g_Kraw[TLEN * KVDIM];
__device__ __half g_Qh  [QLEN * QKDIM];
__device__ __half g_Kh  [TLEN * KVDIM];
__device__ __half g_Vh  [TLEN * KVDIM];
__device__ __half g_Oh  [QLEN * QKDIM];

// ---------------- helpers ----------------
__device__ __forceinline__ uint32_t smem_u32(const void* p) {
    return (uint32_t)__cvta_generic_to_shared(p);
}
__device__ __forceinline__ void ldsm4(uint32_t& r0, uint32_t& r1, uint32_t& r2, uint32_t& r3, uint32_t a) {
    asm volatile("ldmatrix.sync.aligned.m8n8.x4.shared.b16 {%0,%1,%2,%3},[%4];\n"
                 : "=r"(r0), "=r"(r1), "=r"(r2), "=r"(r3) : "r"(a));
}
__device__ __forceinline__ void ldsm4t(uint32_t& r0, uint32_t& r1, uint32_t& r2, uint32_t& r3, uint32_t a) {
    asm volatile("ldmatrix.sync.aligned.m8n8.x4.trans.shared.b16 {%0,%1,%2,%3},[%4];\n"
                 : "=r"(r0), "=r"(r1), "=r"(r2), "=r"(r3) : "r"(a));
}
__device__ __forceinline__ void mma16816(float* c, uint32_t a0, uint32_t a1, uint32_t a2, uint32_t a3,
                                         uint32_t b0, uint32_t b1) {
    asm volatile("mma.sync.aligned.m16n8k16.row.col.f32.f16.f16.f32 "
                 "{%0,%1,%2,%3},{%4,%5,%6,%7},{%8,%9},{%0,%1,%2,%3};\n"
                 : "+f"(c[0]), "+f"(c[1]), "+f"(c[2]), "+f"(c[3])
                 : "r"(a0), "r"(a1), "r"(a2), "r"(a3), "r"(b0), "r"(b1));
}
__device__ __forceinline__ uint32_t packh2(float a, float b) {
    __half2 h = __floats2half2_rn(a, b);
    return *reinterpret_cast<uint32_t*>(&h);
}
__device__ __forceinline__ uint32_t h2exp2(uint32_t x) {
    uint32_t r;
    asm("ex2.approx.f16x2 %0, %1;" : "=r"(r) : "r"(x));
    return r;
}
__device__ __forceinline__ void cpa16(uint32_t dst, const void* src) {
    asm volatile("cp.async.cg.shared.global [%0],[%1],16;\n" :: "r"(dst), "l"(src));
}
__device__ __forceinline__ void cpa_commit() { asm volatile("cp.async.commit_group;\n"); }
template <int N> __device__ __forceinline__ void cpa_wait() {
    asm volatile("cp.async.wait_group %0;\n" :: "n"(N));
}
__device__ __forceinline__ void st2(float* p, float a, float b) { *(float2*)p = make_float2(a, b); }
__device__ __forceinline__ void st2(__half* p, float a, float b) { *(__half2*)p = __floats2half2_rn(a, b); }

// ---------------- fused fp32 -> fp16 conversion: 6 segments, 2x float4/thread ------
__global__ void cvt6(const float* s0, __half* d0, int n0, const float* s1, __half* d1, int n1,
                     const float* s2, __half* d2, int n2, const float* s3, __half* d3, int n3,
                     const float* s4, __half* d4, int n4c, const float* s5, __half* d5, int n5) {
    int total = n0 + n1 + n2 + n3 + n4c + n5;
    int stride = gridDim.x * blockDim.x;
    for (int i = blockIdx.x * blockDim.x + threadIdx.x; i < total; i += stride) {
        const float* s; __half* d; int j = i;
        if (j < n0) { s = s0; d = d0; }
        else if ((j -= n0) < n1) { s = s1; d = d1; }
        else if ((j -= n1) < n2) { s = s2; d = d2; }
        else if ((j -= n2) < n3) { s = s3; d = d3; }
        else if ((j -= n3) < n4c) { s = s4; d = d4; }
        else { j -= n4c; s = s5; d = d5; }
        float4 a = reinterpret_cast<const float4*>(s)[2 * j];
        float4 b = reinterpret_cast<const float4*>(s)[2 * j + 1];
        __half2 h0 = __floats2half2_rn(a.x, a.y), h1 = __floats2half2_rn(a.z, a.w);
        __half2 h2 = __floats2half2_rn(b.x, b.y), h3 = __floats2half2_rn(b.z, b.w);
        uint4 o;
        o.x = *(uint32_t*)&h0; o.y = *(uint32_t*)&h1; o.z = *(uint32_t*)&h2; o.w = *(uint32_t*)&h3;
        reinterpret_cast<uint4*>(d)[j] = o;
    }
}

// =========================================================================
// Merged Q+KV projection (unchanged from round 8)
// =========================================================================
#define GSA 40
#define G_STAGES 3
#define G_ASTRIDE (128 * GSA)
#define G_SMEM128 (G_STAGES * G_ASTRIDE * 2 * 2)

__global__ __launch_bounds__(256, 2) void gemm_qkv(const __half* __restrict__ Xh,
                                                   const __half* __restrict__ Wqh,
                                                   const __half* __restrict__ Wkvh,
                                                   float* __restrict__ Qraw,
                                                   float* __restrict__ Kraw,
                                                   __half* __restrict__ Vh) {
    extern __shared__ __align__(16) __half gsm[];
    __half* As = gsm;
    __half* Bs = gsm + G_STAGES * G_ASTRIDE;
    const int tid = threadIdx.x, lane = tid & 31, w = tid >> 5;
    const int bid = blockIdx.x;
    const bool isQ = bid < 256;
    const __half* A;
    const __half* B;
    int bm, bn;
    if (isQ) {
        A = Xh + (size_t)CTXLEN * HIDDEN;
        B = Wqh;
        bm = (bid >> 5) << 7;
        bn = (bid & 31) << 7;
    } else {
        int b = bid - 256;
        A = Xh;
        B = Wkvh;
        bm = (b >> 4) << 7;
        bn = (b & 15) << 7;
    }
    const int wm = (w >> 1) << 5, wn = (w & 1) << 6;
    constexpr int K = HIDDEN;

    float acc[2][8][4];
#pragma unroll
    for (int i = 0; i < 2; i++)
#pragma unroll
        for (int j = 0; j < 8; j++)
#pragma unroll
            for (int k = 0; k < 4; k++) acc[i][j][k] = 0.f;

    const int r = tid >> 2, cch = (tid & 3) << 3;
    const int nt = K >> 5;

    auto load_stage = [&](int t, int s) {
        int k0 = t << 5;
        cpa16(smem_u32(&As[s * G_ASTRIDE + r * GSA + cch]),        &A[(size_t)(bm + r) * K + k0 + cch]);
        cpa16(smem_u32(&As[s * G_ASTRIDE + (r + 64) * GSA + cch]), &A[(size_t)(bm + r + 64) * K + k0 + cch]);
        cpa16(smem_u32(&Bs[s * G_ASTRIDE + r * GSA + cch]),        &B[(size_t)(bn + r) * K + k0 + cch]);
        cpa16(smem_u32(&Bs[s * G_ASTRIDE + (r + 64) * GSA + cch]), &B[(size_t)(bn + r + 64) * K + k0 + cch]);
    };

    load_stage(0, 0); cpa_commit();
    load_stage(1, 1); cpa_commit();

    int s_cur = 0, s_pre = 2;
    for (int t = 0; t < nt; t++) {
        cpa_wait<1>();
        __syncthreads();
        if (t + 2 < nt) load_stage(t + 2, s_pre);
        cpa_commit();

        const __half* as = As + s_cur * G_ASTRIDE;
        const __half* bs = Bs + s_cur * G_ASTRIDE;
#pragma unroll
        for (int kk = 0; kk < 2; kk++) {
            uint32_t a[2][4];
#pragma unroll
            for (int mt = 0; mt < 2; mt++) {
                uint32_t ad = smem_u32(&as[(wm + mt * 16 + (lane & 15)) * GSA + kk * 16 + ((lane >> 4) << 3)]);
                ldsm4(a[mt][0], a[mt][1], a[mt][2], a[mt][3], ad);
            }
#pragma unroll
            for (int n2 = 0; n2 < 4; n2++) {
                uint32_t b0, b1, b2, b3;
                uint32_t ad = smem_u32(&bs[(wn + n2 * 16 + ((lane >> 4) << 3) + (lane & 7)) * GSA +
                                           kk * 16 + (((lane >> 3) & 1) << 3)]);
                ldsm4(b0, b1, b2, b3, ad);
#pragma unroll
                for (int mt = 0; mt < 2; mt++) {
                    mma16816(acc[mt][2 * n2],     a[mt][0], a[mt][1], a[mt][2], a[mt][3], b0, b1);
                    mma16816(acc[mt][2 * n2 + 1], a[mt][0], a[mt][1], a[mt][2], a[mt][3], b2, b3);
                }
            }
        }
        s_pre = s_cur;
        s_cur = (s_cur == G_STAGES - 1) ? 0 : s_cur + 1;
    }

    const int g = lane >> 2, c = (lane & 3) << 1;
    if (isQ) {
#pragma unroll
        for (int mt = 0; mt < 2; mt++)
#pragma unroll
            for (int ntl = 0; ntl < 8; ntl++) {
                int row = bm + wm + mt * 16 + g;
                int col = bn + wn + ntl * 8 + c;
                st2(&Qraw[(size_t)row * QKDIM + col],       acc[mt][ntl][0], acc[mt][ntl][1]);
                st2(&Qraw[(size_t)(row + 8) * QKDIM + col], acc[mt][ntl][2], acc[mt][ntl][3]);
            }
    } else {
        const bool isK = bn < KVDIM;
        const int colbase = bn - (isK ? 0 : KVDIM) + wn;
#pragma unroll
        for (int mt = 0; mt < 2; mt++)
#pragma unroll
            for (int ntl = 0; ntl < 8; ntl++) {
                int row = bm + wm + mt * 16 + g;
                int col = colbase + ntl * 8 + c;
                if (isK) {
                    st2(&Kraw[(size_t)row * KVDIM + col],       acc[mt][ntl][0], acc[mt][ntl][1]);
                    st2(&Kraw[(size_t)(row + 8) * KVDIM + col], acc[mt][ntl][2], acc[mt][ntl][3]);
                } else {
                    st2(&Vh[(size_t)row * KVDIM + col],       acc[mt][ntl][0], acc[mt][ntl][1]);
                    st2(&Vh[(size_t)(row + 8) * KVDIM + col], acc[mt][ntl][2], acc[mt][ntl][3]);
                }
            }
    }
}

// ---------------- O-projection GEMM (BN=64, unchanged) ----------------
#define GO_SMEM (G_STAGES * (128 + 64) * GSA * 2)
__global__ __launch_bounds__(256, 2) void gemm_o(const __half* __restrict__ A,
                                                 const __half* __restrict__ B,
                                                 float* __restrict__ C) {
    constexpr int NB = 64, BSTRIDE = NB * GSA, K = QKDIM, N = HIDDEN;
    extern __shared__ __align__(16) __half gsm[];
    __half* As = gsm;
    __half* Bs = gsm + G_STAGES * G_ASTRIDE;
    const int tid = threadIdx.x, lane = tid & 31, w = tid >> 5;
    const int bm = blockIdx.y << 7, bn = blockIdx.x * NB;
    const int wm = (w >> 1) << 5, wn = (w & 1) << 5;

    float acc[2][4][4];
#pragma unroll
    for (int i = 0; i < 2; i++)
#pragma unroll
        for (int j = 0; j < 4; j++)
#pragma unroll
            for (int k = 0; k < 4; k++) acc[i][j][k] = 0.f;

    const int r = tid >> 2, cch = (tid & 3) << 3;
    const int nt = K >> 5;

    auto load_stage = [&](int t, int s) {
        int k0 = t << 5;
        cpa16(smem_u32(&As[s * G_ASTRIDE + r * GSA + cch]),        &A[(size_t)(bm + r) * K + k0 + cch]);
        cpa16(smem_u32(&As[s * G_ASTRIDE + (r + 64) * GSA + cch]), &A[(size_t)(bm + r + 64) * K + k0 + cch]);
        cpa16(smem_u32(&Bs[s * BSTRIDE + r * GSA + cch]),          &B[(size_t)(bn + r) * K + k0 + cch]);
    };

    load_stage(0, 0); cpa_commit();
    load_stage(1, 1); cpa_commit();

    int s_cur = 0, s_pre = 2;
    for (int t = 0; t < nt; t++) {
        cpa_wait<1>();
        __syncthreads();
        if (t + 2 < nt) load_stage(t + 2, s_pre);
        cpa_commit();

        const __half* as = As + s_cur * G_ASTRIDE;
        const __half* bs = Bs + s_cur * BSTRIDE;
#pragma unroll
        for (int kk = 0; kk < 2; kk++) {
            uint32_t a[2][4];
#pragma unroll
            for (int mt = 0; mt < 2; mt++) {
                uint32_t ad = smem_u32(&as[(wm + mt * 16 + (lane & 15)) * GSA + kk * 16 + ((lane >> 4) << 3)]);
                ldsm4(a[mt][0], a[mt][1], a[mt][2], a[mt][3], ad);
            }
#pragma unroll
            for (int n2 = 0; n2 < 2; n2++) {
                uint32_t b0, b1, b2, b3;
                uint32_t ad = smem_u32(&bs[(wn + n2 * 16 + ((lane >> 4) << 3) + (lane & 7)) * GSA +
                                           kk * 16 + (((lane >> 3) & 1) << 3)]);
                ldsm4(b0, b1, b2, b3, ad);
#pragma unroll
                for (int mt = 0; mt < 2; mt++) {
                    mma16816(acc[mt][2 * n2],     a[mt][0], a[mt][1], a[mt][2], a[mt][3], b0, b1);
                    mma16816(acc[mt][2 * n2 + 1], a[mt][0], a[mt][1], a[mt][2], a[mt][3], b2, b3);
                }
            }
        }
        s_pre = s_cur;
        s_cur = (s_cur == G_STAGES - 1) ? 0 : s_cur + 1;
    }

    const int g = lane >> 2, c = (lane & 3) << 1;
#pragma unroll
    for (int mt = 0; mt < 2; mt++)
#pragma unroll
        for (int ntl = 0; ntl < 4; ntl++) {
            int row = bm + wm + mt * 16 + g;
            int col = bn + wn + ntl * 8 + c;
            st2(&C[(size_t)row * N + col],       acc[mt][ntl][0], acc[mt][ntl][1]);
            st2(&C[(size_t)(row + 8) * N + col], acc[mt][ntl][2], acc[mt][ntl][3]);
        }
}

// ---------------- merged RMSNorm + RoPE (unchanged) ----------------
__global__ void norm_rope2(const float* __restrict__ Qraw, const float* __restrict__ Kraw,
                           const float* __restrict__ cosp, const float* __restrict__ sinp,
                           const float* __restrict__ qw, const float* __restrict__ kw,
                           __half* __restrict__ Qh, __half* __restrict__ Kh) {
    const int bid = blockIdx.x, d = threadIdx.x;
    const float* src; const float* wnorm; __half* dst;
    int row, h, nheads, pos;
    float outscale;
    if (bid < QLEN * H_HEADS) {
        row = bid >> 5; h = bid & 31; nheads = H_HEADS;
        src = Qraw; wnorm = qw; dst = Qh;
        pos = CTXLEN + row;
        outscale = 0.08838834764831845f * 1.4426950408889634f;
    } else {
        int b = bid - QLEN * H_HEADS;
        row = b >> 3; h = b & 7; nheads = KV_HEADS;
        src = Kraw; wnorm = kw; dst = Kh;
        pos = row;
        outscale = 1.0f;
    }
    const size_t base = (size_t)row * nheads * HEAD_DIM + h * HEAD_DIM;
    float x = src[base + d];
    float ss = x * x;
#pragma unroll
    for (int o = 16; o; o >>= 1) ss += __shfl_xor_sync(0xffffffffu, ss, o);
    __shared__ float ws[4];
    const int lane = d & 31, warp = d >> 5;
    if (lane == 0) ws[warp] = ss;
    __syncthreads();
    float sum = ws[0] + ws[1] + ws[2] + ws[3];
    float y = x * rsqrtf(sum * (1.0f / HEAD_DIM) + 1e-6f) * wnorm[d];
    __shared__ float ys[HEAD_DIM];
    ys[d] = y;
    __syncthreads();
    float partner = (d < 64) ? -ys[d + 64] : ys[d - 64];
    float o = y * cosp[pos * HEAD_DIM + d] + partner * sinp[pos * HEAD_DIM + d];
    dst[base + d] = __float2half(o * outscale);
}

// ---------------- flash attention: 64 q/CTA, 4 warps, 2 CTAs/SM ----------------
#define FPAD 136
#define F_SMEM (4 * 64 * FPAD * 2)     // sK[2][64*FPAD] + sV[2][64*FPAD] halves
__global__ __launch_bounds__(128) void flash(const __half* __restrict__ Qh,
                                             const __half* __restrict__ Kh,
                                             const __half* __restrict__ Vh,
                                             __half* __restrict__ Oh) {
    extern __shared__ __align__(16) __half fsm[];
    __half* sK = fsm;
    __half* sV = fsm + 2 * 64 * FPAD;
    const int tid = threadIdx.x, lane = tid & 31, w = tid >> 5;
    const int bx = gridDim.x - 1 - blockIdx.x;   // heavy blocks first
    const int qb = bx << 6;                      // 64 queries
    const int h = blockIdx.y;
    const int kv = h >> 2;

    // stage Q (64 x 128) through sK, keep as register fragments
    {
        const __half* Qp = Qh + (size_t)qb * QKDIM + h * HEAD_DIM;
        for (int i = tid; i < 64 * 16; i += 128) {
            int r = i >> 4, c = (i & 15) << 3;
            *(uint4*)&sK[r * FPAD + c] = *(const uint4*)&Qp[(size_t)r * QKDIM + c];
        }
    }
    __syncthreads();
    uint32_t qa[8][4];
#pragma unroll
    for (int kt = 0; kt < 8; kt++) {
        uint32_t ad = smem_u32(&sK[(w * 16 + (lane & 15)) * FPAD + kt * 16 + ((lane >> 4) << 3)]);
        ldsm4(qa[kt][0], qa[kt][1], qa[kt][2], qa[kt][3], ad);
    }
    __syncthreads();

    float O[16][4];
#pragma unroll
    for (int i = 0; i < 16; i++)
#pragma unroll
        for (int j = 0; j < 4; j++) O[i][j] = 0.f;
    float lacc[4] = {0.f, 0.f, 0.f, 0.f};
    float m0 = -1e30f, m1 = -1e30f;

    const int ntiles = 33 + bx;
    const __half* Kp = Kh + kv * HEAD_DIM;
    const __half* Vp = Vh + kv * HEAD_DIM;
    const int g = lane >> 2, c2 = (lane & 3) << 1;
    const uint32_t ONE2 = 0x3C003C00u;

    auto loadKV = [&](int t, int buf) {
        for (int i = tid; i < 64 * 16; i += 128) {
            int r = i >> 4, c = (i & 15) << 3;
            size_t go = (size_t)(t * 64 + r) * KVDIM + c;
            cpa16(smem_u32(&sK[(buf * 64 + r) * FPAD + c]), &Kp[go]);
            cpa16(smem_u32(&sV[(buf * 64 + r) * FPAD + c]), &Vp[go]);
        }
    };

    loadKV(0, 0);
    cpa_commit();

    for (int t = 0; t < ntiles; t++) {
        if (t + 1 < ntiles) loadKV(t + 1, (t + 1) & 1);
        cpa_commit();
        cpa_wait<1>();
        __syncthreads();
        const int buf = t & 1;
        const int krel0 = t * 64 - (CTXLEN + qb);   // first key col rel to q row 0

        if (krel0 <= w * 16 + 15) {
            float S[8][4];
#pragma unroll
            for (int i = 0; i < 8; i++)
#pragma unroll
                for (int j = 0; j < 4; j++) S[i][j] = 0.f;

#pragma unroll
            for (int kt = 0; kt < 8; kt++) {
#pragma unroll
                for (int n2 = 0; n2 < 4; n2++) {
                    uint32_t b0, b1, b2, b3;
                    uint32_t ad = smem_u32(&sK[(buf * 64 + n2 * 16 + ((lane >> 4) << 3) + (lane & 7)) * FPAD +
                                               kt * 16 + (((lane >> 3) & 1) << 3)]);
                    ldsm4(b0, b1, b2, b3, ad);
                    mma16816(S[2 * n2],     qa[kt][0], qa[kt][1], qa[kt][2], qa[kt][3], b0, b1);
                    mma16816(S[2 * n2 + 1], qa[kt][0], qa[kt][1], qa[kt][2], qa[kt][3], b2, b3);
                }
            }

            if (krel0 + 63 > w * 16) {
                int r0 = w * 16 + g - krel0, r1 = r0 + 8;
#pragma unroll
                for (int ntl = 0; ntl < 8; ntl++) {
                    int col = ntl * 8 + c2;
                    if (col     > r0) S[ntl][0] = -1e30f;
                    if (col + 1 > r0) S[ntl][1] = -1e30f;
                    if (col     > r1) S[ntl][2] = -1e30f;
                    if (col + 1 > r1) S[ntl][3] = -1e30f;
                }
            }

            float mt0 = -1e30f, mt1 = -1e30f;
#pragma unroll
            for (int ntl = 0; ntl < 8; ntl++) {
                mt0 = fmaxf(mt0, fmaxf(S[ntl][0], S[ntl][1]));
                mt1 = fmaxf(mt1, fmaxf(S[ntl][2], S[ntl][3]));
            }
            mt0 = fmaxf(mt0, __shfl_xor_sync(0xffffffffu, mt0, 1));
            mt0 = fmaxf(mt0, __shfl_xor_sync(0xffffffffu, mt0, 2));
            mt1 = fmaxf(mt1, __shfl_xor_sync(0xffffffffu, mt1, 1));
            mt1 = fmaxf(mt1, __shfl_xor_sync(0xffffffffu, mt1, 2));
            float mn0 = fmaxf(m0, mt0), mn1 = fmaxf(m1, mt1);

            uint32_t P[8][2];
#pragma unroll
            for (int ntl = 0; ntl < 8; ntl++) {
                P[ntl][0] = h2exp2(packh2(S[ntl][0] - mn0, S[ntl][1] - mn0));
                P[ntl][1] = h2exp2(packh2(S[ntl][2] - mn1, S[ntl][3] - mn1));
            }

            if (mn0 > m0 || mn1 > m1) {
                float a0 = exp2f(m0 - mn0), a1 = exp2f(m1 - mn1);
                lacc[0] *= a0; lacc[1] *= a0; lacc[2] *= a1; lacc[3] *= a1;
#pragma unroll
                for (int ntl = 0; ntl < 16; ntl++) {
                    O[ntl][0] *= a0; O[ntl][1] *= a0; O[ntl][2] *= a1; O[ntl][3] *= a1;
                }
            }
            m0 = mn0; m1 = mn1;

#pragma unroll
            for (int kc = 0; kc < 4; kc++) {
                uint32_t A0 = P[2 * kc][0],     A1 = P[2 * kc][1];
                uint32_t A2 = P[2 * kc + 1][0], A3 = P[2 * kc + 1][1];
                mma16816(lacc, A0, A1, A2, A3, ONE2, ONE2);
#pragma unroll
                for (int d2 = 0; d2 < 8; d2++) {
                    uint32_t v0, v1, v2, v3;
                    uint32_t ad = smem_u32(&sV[(buf * 64 + kc * 16 + (lane & 15)) * FPAD +
                                               d2 * 16 + ((lane >> 4) << 3)]);
                    ldsm4t(v0, v1, v2, v3, ad);
                    mma16816(O[2 * d2],     A0, A1, A2, A3, v0, v1);
                    mma16816(O[2 * d2 + 1], A0, A1, A2, A3, v2, v3);
                }
            }
        }
        __syncthreads();
    }

    float i0 = 1.f / lacc[0], i1 = 1.f / lacc[2];
    __half* Op = Oh + (size_t)(qb + w * 16) * QKDIM + h * HEAD_DIM;
#pragma unroll
    for (int ntl = 0; ntl < 16; ntl++) {
        int col = ntl * 8 + c2;
        *(__half2*)&Op[(size_t)g * QKDIM + col]       = __floats2half2_rn(O[ntl][0] * i0, O[ntl][1] * i0);
        *(__half2*)&Op[(size_t)(g + 8) * QKDIM + col] = __floats2half2_rn(O[ntl][2] * i1, O[ntl][3] * i1);
    }
}

// ---------------- launcher ----------------
extern "C" void kernel_launch(void* const* d_in, const int* in_sizes, int n_in,
                              void* d_out, int out_size) {
    const float* hidden = (const float*)d_in[0];
    const float* target = (const float*)d_in[1];
    const float* cosp   = (const float*)d_in[2];
    const float* sinp   = (const float*)d_in[3];
    const float* wq = (const float*)d_in[5];
    const float* wk = (const float*)d_in[6];
    const float* wv = (const float*)d_in[7];
    const float* wo = (const float*)d_in[8];
    const float* qw = (const float*)d_in[9];
    const float* kw = (const float*)d_in[10];
    float* out = (float*)d_out;

    __half *Xh, *Wqh, *Wkvh, *Woh, *Qh, *Kh, *Vh, *Oh;
    float *Qraw, *Kraw;
    cudaGetSymbolAddress((void**)&Xh, g_Xh);
    cudaGetSymbolAddress((void**)&Wqh, g_Wqh);
    cudaGetSymbolAddress((void**)&Wkvh, g_Wkvh);
    cudaGetSymbolAddress((void**)&Woh, g_Woh);
    cudaGetSymbolAddress((void**)&Qraw, g_Qraw);
    cudaGetSymbolAddress((void**)&Kraw, g_Kraw);
    cudaGetSymbolAddress((void**)&Qh, g_Qh);
    cudaGetSymbolAddress((void**)&Kh, g_Kh);
    cudaGetSymbolAddress((void**)&Vh, g_Vh);
    cudaGetSymbolAddress((void**)&Oh, g_Oh);

    cudaFuncSetAttribute((const void*)gemm_qkv, cudaFuncAttributeMaxDynamicSharedMemorySize, G_SMEM128);
    cudaFuncSetAttribute((const void*)gemm_o,   cudaFuncAttributeMaxDynamicSharedMemorySize, GO_SMEM);
    cudaFuncSetAttribute((const void*)flash,    cudaFuncAttributeMaxDynamicSharedMemorySize, F_SMEM);

    cvt6<<<1184, 256>>>(target, Xh, CTXLEN * HIDDEN / 8,
                        hidden, Xh + (size_t)CTXLEN * HIDDEN, QLEN * HIDDEN / 8,
                        wq, Wqh, QKDIM * HIDDEN / 8,
                        wk, Wkvh, KVDIM * HIDDEN / 8,
                        wv, Wkvh + (size_t)KVDIM * HIDDEN, KVDIM * HIDDEN / 8,
                        wo, Woh, HIDDEN * QKDIM / 8);

    gemm_qkv<<<640, 256, G_SMEM128>>>(Xh, Wqh, Wkvh, Qraw, Kraw, Vh);

    norm_rope2<<<QLEN * H_HEADS + TLEN * KV_HEADS, 128>>>(Qraw, Kraw, cosp, sinp, qw, kw, Qh, Kh);

    // 64 queries per CTA, 4 warps; 2 CTAs co-resident per SM
    flash<<<dim3(QLEN / 64, H_HEADS), 128, F_SMEM>>>(Qh, Kh, Vh, Oh);

    gemm_o<<<dim3(HIDDEN / 64, QLEN / 128), 256, GO_SMEM>>>(Oh, Woh, out);
}